// round 12
// baseline (speedup 1.0000x reference)
#include <cuda_runtime.h>
#include <cuda_fp16.h>
#include <math.h>
#include <stdint.h>

// ---------------------------------------------------------------------------
// Problem constants
// ---------------------------------------------------------------------------
#define BATCH     2
#define SEQ       2048
#define DMODEL    4096
#define NHEADS    32
#define KVHEADS   8
#define HEADDIM   128
#define QKV_N     (DMODEL + 2 * KVHEADS * HEADDIM)   // 6144
#define TOKENS    (BATCH * SEQ)                      // 4096
#define CLIP_V    8.0f
#define INV_SQRT_D 0.08838834764831845f

// ---------------------------------------------------------------------------
// Scratch (device globals) — fp16 operands
// ---------------------------------------------------------------------------
__device__ __half g_qkv [(size_t)TOKENS * QKV_N];
__device__ __half g_q   [(size_t)BATCH * NHEADS  * SEQ * HEADDIM];
__device__ __half g_k   [(size_t)BATCH * KVHEADS * SEQ * HEADDIM];
__device__ __half g_vt  [(size_t)BATCH * KVHEADS * HEADDIM * SEQ];
__device__ __half g_attn[(size_t)TOKENS * DMODEL];
__device__ __half g_hid [(size_t)TOKENS * DMODEL];
__device__ __half g_wq  [(size_t)QKV_N  * DMODEL];
__device__ __half g_wo  [(size_t)DMODEL * DMODEL];

// ---------------------------------------------------------------------------
// helpers
// ---------------------------------------------------------------------------
__device__ __forceinline__ void mma_f16(float* c, const uint32_t* a, const uint32_t* b) {
    asm volatile(
        "mma.sync.aligned.m16n8k16.row.col.f32.f16.f16.f32 "
        "{%0,%1,%2,%3}, {%4,%5,%6,%7}, {%8,%9}, {%0,%1,%2,%3};"
        : "+f"(c[0]), "+f"(c[1]), "+f"(c[2]), "+f"(c[3])
        : "r"(a[0]), "r"(a[1]), "r"(a[2]), "r"(a[3]), "r"(b[0]), "r"(b[1]));
}
__device__ __forceinline__ void cp16(uint32_t s, const void* g) {
    asm volatile("cp.async.cg.shared.global [%0], [%1], 16;" :: "r"(s), "l"(g));
}
__device__ __forceinline__ void ldsm_x4(uint32_t* r, uint32_t addr) {
    asm volatile("ldmatrix.sync.aligned.m8n8.x4.shared.b16 {%0,%1,%2,%3}, [%4];"
                 : "=r"(r[0]), "=r"(r[1]), "=r"(r[2]), "=r"(r[3]) : "r"(addr));
}

// ---------------------------------------------------------------------------
// elementwise f32 -> fp16 round
// ---------------------------------------------------------------------------
__global__ __launch_bounds__(256)
void round_h_kernel(const float4* __restrict__ in, half2* __restrict__ out, int n4)
{
    for (int i = blockIdx.x * blockDim.x + threadIdx.x; i < n4; i += gridDim.x * blockDim.x) {
        float4 v = in[i];
        out[2 * i]     = __floats2half2_rn(v.x, v.y);
        out[2 * i + 1] = __floats2half2_rn(v.z, v.w);
    }
}

// ---------------------------------------------------------------------------
// FP16 tensor-core GEMM:  C[M,N] = A[M,K] * B[N,K]^T
// 128x128x64 block tile, 4 warps (2x2), warp tile 64x64, m16n8k16 mma.
// 3-stage cp.async pipeline (110,592 B -> 2 CTAs/SM at 128 threads).
// 8 ldsm -> 32 mmas per k-step (was 6 -> 16): higher tensor-pipe density.
// ---------------------------------------------------------------------------
#define BM 128
#define BN 128
#define HBK 64
#define HKP 72
#define STAGE_HALVES (BM * HKP + BN * HKP)            // 18,432 halves
#define GEMM_SMEM_BYTES (3 * STAGE_HALVES * 2)        // 110,592
#define EPP 68                                        // f32 epilogue pitch (272B rows)

template <bool DO_CLIP, bool OUT_HALF>
__global__ __launch_bounds__(128, 2)
void gemm_f16(const __half* __restrict__ A, const __half* __restrict__ B,
              void* __restrict__ Cv, int M, int N, int K)
{
    extern __shared__ char smc[];
    const uint32_t smem_base = (uint32_t)__cvta_generic_to_shared(smc);

    const int tid = threadIdx.x;
    const int ln  = tid & 31;
    const int wid = tid >> 5;          // 0..3
    const int wm  = wid >> 1;          // 0..1
    const int wn  = wid & 1;           // 0..1
    const int m0  = blockIdx.y * BM;
    const int n0  = blockIdx.x * BN;
    const int lq  = ln >> 2;
    const int lr  = ln & 3;

    const uint32_t a_lane = (uint32_t)(((wm * 64 + (ln & 15)) * HKP + (ln >> 4) * 8) * 2);
    const uint32_t b_lane = (uint32_t)(((wn * 64 + (ln >> 4) * 8 + (ln & 7)) * HKP
                                        + ((ln >> 3) & 1) * 8) * 2);

    const __half* Abase = A + (size_t)m0 * K;
    const __half* Bbase = B + (size_t)n0 * K;

    auto load_stage = [&](int kt, int s) {
        const __half* Ag = Abase + kt * HBK;
        const __half* Bg = Bbase + kt * HBK;
        const uint32_t sa = smem_base + (uint32_t)(s * STAGE_HALVES) * 2u;
        const uint32_t sb = sa + BM * HKP * 2u;
        #pragma unroll
        for (int r = 0; r < 8; r++) {                 // 1024 A + 1024 B chunks
            const int i   = r * 128 + tid;
            const int row = i >> 3;
            const int kc  = (i & 7) << 3;             // halves
            cp16(sa + (uint32_t)(row * HKP + kc) * 2u, Ag + (size_t)row * K + kc);
            cp16(sb + (uint32_t)(row * HKP + kc) * 2u, Bg + (size_t)row * K + kc);
        }
        asm volatile("cp.async.commit_group;");
    };

    load_stage(0, 0);
    load_stage(1, 1);

    float acc[4][8][4];
    #pragma unroll
    for (int a = 0; a < 4; a++)
        #pragma unroll
        for (int b = 0; b < 8; b++)
            #pragma unroll
            for (int c = 0; c < 4; c++) acc[a][b][c] = 0.0f;

    const int nk = K / HBK;
    for (int kt = 0; kt < nk; kt++) {
        asm volatile("cp.async.wait_group 1;");
        __syncthreads();

        if (kt + 2 < nk) load_stage(kt + 2, (kt + 2) % 3);
        else             asm volatile("cp.async.commit_group;");

        const uint32_t st = smem_base + (uint32_t)((kt % 3) * STAGE_HALVES) * 2u;
        const uint32_t aa = st + a_lane;
        const uint32_t bb = st + BM * HKP * 2u + b_lane;

        #pragma unroll
        for (int ks = 0; ks < 4; ks++) {
            const uint32_t k0b = (uint32_t)(ks * 32);
            uint32_t af[4][4], bf[4][4];
            #pragma unroll
            for (int mt = 0; mt < 4; mt++)
                ldsm_x4(af[mt], aa + (uint32_t)(mt * 16 * HKP * 2) + k0b);
            #pragma unroll
            for (int p = 0; p < 4; p++)
                ldsm_x4(bf[p], bb + (uint32_t)(p * 16 * HKP * 2) + k0b);
            #pragma unroll
            for (int mt = 0; mt < 4; mt++)
                #pragma unroll
                for (int p = 0; p < 4; p++) {
                    mma_f16(acc[mt][2 * p],     af[mt], &bf[p][0]);
                    mma_f16(acc[mt][2 * p + 1], af[mt], &bf[p][2]);
                }
        }
    }
    __syncthreads();

    if (OUT_HALF) {
        __half* C = (__half*)Cv;
        #pragma unroll
        for (int mt = 0; mt < 4; mt++) {
            #pragma unroll
            for (int nt = 0; nt < 8; nt++) {
                const int row = m0 + wm * 64 + mt * 16 + lq;
                const int col = n0 + wn * 64 + nt * 8 + lr * 2;
                float x0 = acc[mt][nt][0], x1 = acc[mt][nt][1];
                float x2 = acc[mt][nt][2], x3 = acc[mt][nt][3];
                if (DO_CLIP) {
                    x0 = fminf(fmaxf(x0, -CLIP_V), CLIP_V);
                    x1 = fminf(fmaxf(x1, -CLIP_V), CLIP_V);
                    x2 = fminf(fmaxf(x2, -CLIP_V), CLIP_V);
                    x3 = fminf(fmaxf(x3, -CLIP_V), CLIP_V);
                }
                *(half2*)(C + (size_t)row * N + col)       = __floats2half2_rn(x0, x1);
                *(half2*)(C + (size_t)(row + 8) * N + col) = __floats2half2_rn(x2, x3);
            }
        }
    } else {
        // f32 output staged through smem (per-warp 16x64 tile per pass)
        float* C  = (float*)Cv;
        float* ep = (float*)smc + wid * (16 * EPP);
        #pragma unroll
        for (int mt = 0; mt < 4; mt++) {
            __syncwarp();
            #pragma unroll
            for (int nt = 0; nt < 8; nt++) {
                float* p0 = ep + (lq)     * EPP + nt * 8 + lr * 2;
                float* p1 = ep + (lq + 8) * EPP + nt * 8 + lr * 2;
                p0[0] = acc[mt][nt][0]; p0[1] = acc[mt][nt][1];
                p1[0] = acc[mt][nt][2]; p1[1] = acc[mt][nt][3];
            }
            __syncwarp();
            #pragma unroll
            for (int rr = 0; rr < 8; rr++) {
                const int row = rr * 2 + (ln >> 4);   // 0..15
                const int c4  = (ln & 15) * 4;        // 0..60
                float4 v = *(float4*)&ep[row * EPP + c4];
                *(float4*)(C + (size_t)(m0 + wm * 64 + mt * 16 + row) * N
                             + n0 + wn * 64 + c4) = v;
            }
        }
    }
}

// ---------------------------------------------------------------------------
// RoPE + layout — 64 sincos pairs computed ONCE per token block (smem),
// not once per head (40x MUFU reduction).
// ---------------------------------------------------------------------------
__global__ __launch_bounds__(256)
void rope_kernel()
{
    __shared__ float cs[64], sn[64];

    const int token = blockIdx.x;
    const int b    = token / SEQ;
    const int spos = token - b * SEQ;
    const __half* row = g_qkv + (size_t)token * QKV_N;

    if (threadIdx.x < 64) {
        const int j = threadIdx.x;
        const float freq = __powf(500000.0f, -(float)j * (1.0f / 64.0f));
        sincosf((float)spos * freq, &sn[j], &cs[j]);
    }
    __syncthreads();

    for (int idx = threadIdx.x; idx < (NHEADS + KVHEADS) * 64; idx += 256) {
        const int h = idx >> 6;
        const int j = idx & 63;
        const float s = sn[j], c = cs[j];

        const float x1 = __half2float(row[h * HEADDIM + j]);
        const float x2 = __half2float(row[h * HEADDIM + 64 + j]);
        const float y1 = x1 * c - x2 * s;
        const float y2 = x2 * c + x1 * s;

        if (h < NHEADS) {
            __half* q = g_q + ((size_t)(b * NHEADS + h) * SEQ + spos) * HEADDIM;
            q[j]      = __float2half_rn(y1 * INV_SQRT_D);
            q[j + 64] = __float2half_rn(y2 * INV_SQRT_D);
        } else {
            __half* k = g_k + ((size_t)(b * KVHEADS + (h - NHEADS)) * SEQ + spos) * HEADDIM;
            k[j]      = __float2half_rn(y1);
            k[j + 64] = __float2half_rn(y2);
        }
    }

    const __half* vrow = row + DMODEL + KVHEADS * HEADDIM;
    for (int idx = threadIdx.x; idx < KVHEADS * HEADDIM; idx += 256) {
        const int hk = idx >> 7;
        const int d  = idx & 127;
        g_vt[((size_t)(b * KVHEADS + hk) * HEADDIM + d) * SEQ + spos] = vrow[hk * HEADDIM + d];
    }
}

// ---------------------------------------------------------------------------
// FP16 tensor-core causal flash attention (unchanged from R11 — proven)
// ---------------------------------------------------------------------------
#define AK_PITCH 136
#define AV_PITCH 72
#define AP_PITCH 72
#define AK_BYTES (64 * AK_PITCH * 2)
#define AV_BYTES (128 * AV_PITCH * 2)
#define AP_BYTES (128 * AP_PITCH * 2)
#define ATTN_SMEM_BYTES (2 * AK_BYTES + 2 * AV_BYTES + AP_BYTES)  // 90,112

__global__ __launch_bounds__(256, 1)
void attn_kernel()
{
    extern __shared__ char smc[];
    const uint32_t smem_base = (uint32_t)__cvta_generic_to_shared(smc);
    const uint32_t kb[2] = { smem_base, smem_base + AK_BYTES };
    const uint32_t vb[2] = { smem_base + 2 * AK_BYTES,
                             smem_base + 2 * AK_BYTES + AV_BYTES };
    const uint32_t ps_base = smem_base + 2 * AK_BYTES + 2 * AV_BYTES;
    __half* Ph = (__half*)(smc + 2 * AK_BYTES + 2 * AV_BYTES);

    const int qtile = (SEQ / 128 - 1) - blockIdx.x;
    const int h  = blockIdx.y;
    const int b  = blockIdx.z;
    const int hk = h >> 2;
    const int q0 = qtile * 128;
    const int nj = 2 * qtile + 2;

    const int tid = threadIdx.x;
    const int ln  = tid & 31;
    const int wid = tid >> 5;
    const int lq  = ln >> 2;
    const int lr  = ln & 3;

    const uint32_t a_lane_k = (uint32_t)(((wid * 16 + (ln & 15)) * AK_PITCH
                                          + (ln >> 4) * 8) * 2);
    const uint32_t a_lane_p = (uint32_t)(((wid * 16 + (ln & 15)) * AP_PITCH
                                          + (ln >> 4) * 8) * 2);
    const uint32_t b_lane_k = (uint32_t)((((ln >> 4) * 8 + (ln & 7)) * AK_PITCH
                                          + ((ln >> 3) & 1) * 8) * 2);
    const uint32_t b_lane_v = (uint32_t)((((ln >> 4) * 8 + (ln & 7)) * AV_PITCH
                                          + ((ln >> 3) & 1) * 8) * 2);

    const __half* Qg = g_q  + ((size_t)(b * NHEADS  + h)  * SEQ + q0) * HEADDIM;
    const __half* Kg = g_k  + ((size_t)(b * KVHEADS + hk) * SEQ) * HEADDIM;
    const __half* Vg = g_vt + ((size_t)(b * KVHEADS + hk) * HEADDIM) * SEQ;

    auto load_k = [&](int jt) {
        const int j0 = jt * 64;
        const uint32_t base = kb[jt & 1];
        for (int i = tid; i < 1024; i += 256) {
            const int r  = i >> 4;
            const int c8 = (i & 15) << 3;
            cp16(base + (uint32_t)(r * AK_PITCH + c8) * 2u,
                 Kg + (size_t)(j0 + r) * HEADDIM + c8);
        }
        asm volatile("cp.async.commit_group;");
    };
    auto load_v = [&](int jt) {
        const int j0 = jt * 64;
        const uint32_t base = vb[jt & 1];
        for (int i = tid; i < 1024; i += 256) {
            const int r  = i >> 3;
            const int c8 = (i & 7) << 3;
            cp16(base + (uint32_t)(r * AV_PITCH + c8) * 2u,
                 Vg + (size_t)r * SEQ + j0 + c8);
        }
        asm volatile("cp.async.commit_group;");
    };

    for (int i = tid; i < 2048; i += 256) {
        const int r  = i >> 4;
        const int c8 = (i & 15) << 3;
        cp16(kb[0] + (uint32_t)(r * AK_PITCH + c8) * 2u, Qg + (size_t)r * HEADDIM + c8);
    }
    asm volatile("cp.async.commit_group;");
    asm volatile("cp.async.wait_group 0;");
    __syncthreads();

    uint32_t qf[8][4];
    #pragma unroll
    for (int ks = 0; ks < 8; ks++)
        ldsm_x4(qf[ks], kb[0] + a_lane_k + (uint32_t)(ks * 32));
    __syncthreads();

    load_k(0);
    load_v(0);

    float m0 = -3.0e38f, m1 = -3.0e38f, l0 = 0.0f, l1 = 0.0f;
    float o[16][4];
    #pragma unroll
    for (int nt = 0; nt < 16; nt++)
        #pragma unroll
        for (int c = 0; c < 4; c++) o[nt][c] = 0.0f;

    for (int jt = 0; jt < nj; jt++) {
        asm volatile("cp.async.wait_group 1;");
        __syncthreads();

        float s_[8][4];
        #pragma unroll
        for (int t = 0; t < 8; t++)
            #pragma unroll
            for (int c = 0; c < 4; c++) s_[t][c] = 0.0f;

        const uint32_t kbase = kb[jt & 1] + b_lane_k;
        #pragma unroll
        for (int ks = 0; ks < 8; ks++) {
            const uint32_t k0b = (uint32_t)(ks * 32);
            #pragma unroll
            for (int p = 0; p < 4; p++) {
                uint32_t bt[4];
                ldsm_x4(bt, kbase + (uint32_t)(p * 16 * AK_PITCH * 2) + k0b);
                mma_f16(s_[2 * p],     qf[ks], &bt[0]);
                mma_f16(s_[2 * p + 1], qf[ks], &bt[2]);
            }
        }

        if (jt + 1 < nj) load_k(jt + 1);
        else             asm volatile("cp.async.commit_group;");

        if (jt >= nj - 2) {
            const int rrel  = wid * 16 + lq;
            const int crel0 = (jt - (nj - 2)) * 64;
            #pragma unroll
            for (int t = 0; t < 8; t++) {
                const int c0 = crel0 + t * 8 + 2 * lr;
                if (c0     > rrel)     s_[t][0] = -3.0e38f;
                if (c0 + 1 > rrel)     s_[t][1] = -3.0e38f;
                if (c0     > rrel + 8) s_[t][2] = -3.0e38f;
                if (c0 + 1 > rrel + 8) s_[t][3] = -3.0e38f;
            }
        }

        float mx0 = -3.0e38f, mx1 = -3.0e38f;
        #pragma unroll
        for (int t = 0; t < 8; t++) {
            mx0 = fmaxf(mx0, fmaxf(s_[t][0], s_[t][1]));
            mx1 = fmaxf(mx1, fmaxf(s_[t][2], s_[t][3]));
        }
        mx0 = fmaxf(mx0, __shfl_xor_sync(0xffffffffu, mx0, 1));
        mx0 = fmaxf(mx0, __shfl_xor_sync(0xffffffffu, mx0, 2));
        mx1 = fmaxf(mx1, __shfl_xor_sync(0xffffffffu, mx1, 1));
        mx1 = fmaxf(mx1, __shfl_xor_sync(0xffffffffu, mx1, 2));

        const float mn0 = fmaxf(m0, mx0);
        const float mn1 = fmaxf(m1, mx1);
        const float al0 = __expf(m0 - mn0);
        const float al1 = __expf(m1 - mn1);
        float rs0 = 0.0f, rs1 = 0.0f;
        #pragma unroll
        for (int t = 0; t < 8; t++) {
            s_[t][0] = __expf(s_[t][0] - mn0); rs0 += s_[t][0];
            s_[t][1] = __expf(s_[t][1] - mn0); rs0 += s_[t][1];
            s_[t][2] = __expf(s_[t][2] - mn1); rs1 += s_[t][2];
            s_[t][3] = __expf(s_[t][3] - mn1); rs1 += s_[t][3];
        }
        rs0 += __shfl_xor_sync(0xffffffffu, rs0, 1);
        rs0 += __shfl_xor_sync(0xffffffffu, rs0, 2);
        rs1 += __shfl_xor_sync(0xffffffffu, rs1, 1);
        rs1 += __shfl_xor_sync(0xffffffffu, rs1, 2);
        l0 = l0 * al0 + rs0;  m0 = mn0;
        l1 = l1 * al1 + rs1;  m1 = mn1;
        #pragma unroll
        for (int nt = 0; nt < 16; nt++) {
            o[nt][0] *= al0; o[nt][1] *= al0;
            o[nt][2] *= al1; o[nt][3] *= al1;
        }

        asm volatile("cp.async.wait_group 1;");

        {
            __half* p0 = Ph + (wid * 16 + lq) * AP_PITCH + 2 * lr;
            __half* p1 = p0 + 8 * AP_PITCH;
            #pragma unroll
            for (int t = 0; t < 8; t++) {
                *(half2*)(p0 + t * 8) = __floats2half2_rn(s_[t][0], s_[t][1]);
                *(half2*)(p1 + t * 8) = __floats2half2_rn(s_[t][2], s_[t][3]);
            }
        }
        __syncwarp();

        const uint32_t vbase = vb[jt & 1] + b_lane_v;
        #pragma unroll
        for (int ks = 0; ks < 4; ks++) {
            const uint32_t k0b = (uint32_t)(ks * 32);
            uint32_t a[4];
            ldsm_x4(a, ps_base + a_lane_p + k0b);
            #pragma unroll
            for (int p = 0; p < 8; p++) {
                uint32_t bt[4];
                ldsm_x4(bt, vbase + (uint32_t)(p * 16 * AV_PITCH * 2) + k0b);
                mma_f16(o[2 * p],     a, &bt[0]);
                mma_f16(o[2 * p + 1], a, &bt[2]);
            }
        }

        if (jt + 1 < nj) load_v(jt + 1);
        else             asm volatile("cp.async.commit_group;");
    }

    const float inv0 = 1.0f / l0;
    const float inv1 = 1.0f / l1;
    const int s0 = q0 + wid * 16 + lq;
    __half* O0 = g_attn + (size_t)(b * SEQ + s0) * DMODEL + h * HEADDIM + 2 * lr;
    __half* O1 = O0 + (size_t)8 * DMODEL;
    #pragma unroll
    for (int nt = 0; nt < 16; nt++) {
        *(half2*)(O0 + nt * 8) = __floats2half2_rn(o[nt][0] * inv0, o[nt][1] * inv0);
        *(half2*)(O1 + nt * 8) = __floats2half2_rn(o[nt][2] * inv1, o[nt][3] * inv1);
    }
}

// ---------------------------------------------------------------------------
// Launch sequence
// ---------------------------------------------------------------------------
extern "C" void kernel_launch(void* const* d_in, const int* in_sizes, int n_in,
                              void* d_out, int out_size)
{
    const float* hidden = (const float*)d_in[0];
    const float* Wqkv   = (const float*)d_in[3];
    const float* out_w  = (const float*)d_in[4];
    float*       out    = (float*)d_out;

    __half *qkv_p, *attn_p, *hid_p, *wq_p, *wo_p;
    cudaGetSymbolAddress((void**)&qkv_p,  g_qkv);
    cudaGetSymbolAddress((void**)&attn_p, g_attn);
    cudaGetSymbolAddress((void**)&hid_p,  g_hid);
    cudaGetSymbolAddress((void**)&wq_p,   g_wq);
    cudaGetSymbolAddress((void**)&wo_p,   g_wo);

    cudaFuncSetAttribute((const void*)gemm_f16<true, true>,
                         cudaFuncAttributeMaxDynamicSharedMemorySize, GEMM_SMEM_BYTES);
    cudaFuncSetAttribute((const void*)gemm_f16<false, false>,
                         cudaFuncAttributeMaxDynamicSharedMemorySize, GEMM_SMEM_BYTES);
    cudaFuncSetAttribute((const void*)attn_kernel,
                         cudaFuncAttributeMaxDynamicSharedMemorySize, ATTN_SMEM_BYTES);

    // 0) pre-round operands to fp16
    round_h_kernel<<<1184, 256>>>((const float4*)hidden, (half2*)hid_p,
                                  TOKENS * DMODEL / 4);
    round_h_kernel<<<1184, 256>>>((const float4*)Wqkv, (half2*)wq_p,
                                  QKV_N * DMODEL / 4);
    round_h_kernel<<<1184, 256>>>((const float4*)out_w, (half2*)wo_p,
                                  DMODEL * DMODEL / 4);

    // 1) QKV projection with clip (half output)
    gemm_f16<true, true><<<dim3(QKV_N / BN, TOKENS / BM), 128, GEMM_SMEM_BYTES>>>(
        hid_p, wq_p, qkv_p, TOKENS, QKV_N, DMODEL);

    // 2) RoPE + layouts (fp16 outputs, hoisted sincos)
    rope_kernel<<<TOKENS, 256>>>();

    // 3) fp16 tensor-core causal flash attention
    attn_kernel<<<dim3(SEQ / 128, NHEADS, BATCH), 256, ATTN_SMEM_BYTES>>>();

    // 4) output projection (f32 output)
    gemm_f16<false, false><<<dim3(DMODEL / BN, TOKENS / BM), 128, GEMM_SMEM_BYTES>>>(
        attn_p, wo_p, out, TOKENS, DMODEL, DMODEL);
}

// round 13
// speedup vs baseline: 1.0465x; 1.0465x over previous
#include <cuda_runtime.h>
#include <cuda_fp16.h>
#include <math.h>
#include <stdint.h>

// ---------------------------------------------------------------------------
// Problem constants
// ---------------------------------------------------------------------------
#define BATCH     2
#define SEQ       2048
#define DMODEL    4096
#define NHEADS    32
#define KVHEADS   8
#define HEADDIM   128
#define QKV_N     (DMODEL + 2 * KVHEADS * HEADDIM)   // 6144
#define TOKENS    (BATCH * SEQ)                      // 4096
#define CLIP_V    8.0f
#define INV_SQRT_D 0.08838834764831845f

// ---------------------------------------------------------------------------
// Scratch (device globals) — fp16 operands
// ---------------------------------------------------------------------------
__device__ __half g_qkv [(size_t)TOKENS * QKV_N];
__device__ __half g_q   [(size_t)BATCH * NHEADS  * SEQ * HEADDIM];
__device__ __half g_k   [(size_t)BATCH * KVHEADS * SEQ * HEADDIM];
__device__ __half g_vt  [(size_t)BATCH * KVHEADS * HEADDIM * SEQ];
__device__ __half g_attn[(size_t)TOKENS * DMODEL];
__device__ __half g_hid [(size_t)TOKENS * DMODEL];
__device__ __half g_wq  [(size_t)QKV_N  * DMODEL];
__device__ __half g_wo  [(size_t)DMODEL * DMODEL];

// ---------------------------------------------------------------------------
// helpers
// ---------------------------------------------------------------------------
__device__ __forceinline__ void mma_f16(float* c, const uint32_t* a, const uint32_t* b) {
    asm volatile(
        "mma.sync.aligned.m16n8k16.row.col.f32.f16.f16.f32 "
        "{%0,%1,%2,%3}, {%4,%5,%6,%7}, {%8,%9}, {%0,%1,%2,%3};"
        : "+f"(c[0]), "+f"(c[1]), "+f"(c[2]), "+f"(c[3])
        : "r"(a[0]), "r"(a[1]), "r"(a[2]), "r"(a[3]), "r"(b[0]), "r"(b[1]));
}
__device__ __forceinline__ void cp16(uint32_t s, const void* g) {
    asm volatile("cp.async.cg.shared.global [%0], [%1], 16;" :: "r"(s), "l"(g));
}
__device__ __forceinline__ void ldsm_x4(uint32_t* r, uint32_t addr) {
    asm volatile("ldmatrix.sync.aligned.m8n8.x4.shared.b16 {%0,%1,%2,%3}, [%4];"
                 : "=r"(r[0]), "=r"(r[1]), "=r"(r[2]), "=r"(r[3]) : "r"(addr));
}

// ---------------------------------------------------------------------------
// fused f32 -> fp16 round of hidden + Wqkv + out_w in ONE launch
// (grid-stride across concatenated logical range)
// ---------------------------------------------------------------------------
#define N4_HID (TOKENS * DMODEL / 4)
#define N4_WQ  (QKV_N  * DMODEL / 4)
#define N4_WO  (DMODEL * DMODEL / 4)
#define N4_ALL (N4_HID + N4_WQ + N4_WO)

__global__ __launch_bounds__(256)
void round_all_kernel(const float4* __restrict__ hid, const float4* __restrict__ wq,
                      const float4* __restrict__ wo,
                      half2* __restrict__ hid_o, half2* __restrict__ wq_o,
                      half2* __restrict__ wo_o)
{
    for (int i = blockIdx.x * blockDim.x + threadIdx.x; i < N4_ALL;
         i += gridDim.x * blockDim.x) {
        const float4* src;
        half2* dst;
        int j = i;
        if (j < N4_HID)            { src = hid; dst = hid_o; }
        else if ((j -= N4_HID) < N4_WQ) { src = wq; dst = wq_o; }
        else { j -= N4_WQ;           src = wo;  dst = wo_o; }
        float4 v = src[j];
        dst[2 * j]     = __floats2half2_rn(v.x, v.y);
        dst[2 * j + 1] = __floats2half2_rn(v.z, v.w);
    }
}

// ---------------------------------------------------------------------------
// FP16 tensor-core GEMM (exact R11 config — best measured):
// 128x128x64 block tile, 8 warps (2x4), warp tile 64x32, m16n8k16 mma,
// 3-stage cp.async, one sync per iter, 2 CTAs/SM.
// ---------------------------------------------------------------------------
#define BM 128
#define BN 128
#define HBK 64
#define HKP 72
#define STAGE_HALVES (BM * HKP + BN * HKP)            // 18,432 halves
#define GEMM_SMEM_BYTES (3 * STAGE_HALVES * 2)        // 110,592
#define EP_PITCH 36

template <bool DO_CLIP, bool OUT_HALF>
__global__ __launch_bounds__(256, 2)
void gemm_f16(const __half* __restrict__ A, const __half* __restrict__ B,
              void* __restrict__ Cv, int M, int N, int K)
{
    extern __shared__ char smc[];
    const uint32_t smem_base = (uint32_t)__cvta_generic_to_shared(smc);

    const int tid = threadIdx.x;
    const int ln  = tid & 31;
    const int wid = tid >> 5;
    const int wm  = wid >> 2;
    const int wn  = wid & 3;
    const int m0  = blockIdx.y * BM;
    const int n0  = blockIdx.x * BN;
    const int lq  = ln >> 2;
    const int lr  = ln & 3;

    const uint32_t a_lane = (uint32_t)(((wm * 64 + (ln & 15)) * HKP + (ln >> 4) * 8) * 2);
    const uint32_t b_lane = (uint32_t)(((wn * 32 + (ln >> 4) * 8 + (ln & 7)) * HKP
                                        + ((ln >> 3) & 1) * 8) * 2);

    const __half* Abase = A + (size_t)m0 * K;
    const __half* Bbase = B + (size_t)n0 * K;

    auto load_stage = [&](int kt, int s) {
        const __half* Ag = Abase + kt * HBK;
        const __half* Bg = Bbase + kt * HBK;
        const uint32_t sa = smem_base + (uint32_t)(s * STAGE_HALVES) * 2u;
        const uint32_t sb = sa + BM * HKP * 2u;
        #pragma unroll
        for (int r = 0; r < 4; r++) {
            const int i   = r * 256 + tid;
            const int row = i >> 3;
            const int kc  = (i & 7) << 3;
            cp16(sa + (uint32_t)(row * HKP + kc) * 2u, Ag + (size_t)row * K + kc);
            cp16(sb + (uint32_t)(row * HKP + kc) * 2u, Bg + (size_t)row * K + kc);
        }
        asm volatile("cp.async.commit_group;");
    };

    load_stage(0, 0);
    load_stage(1, 1);

    float acc[4][4][4];
    #pragma unroll
    for (int a = 0; a < 4; a++)
        #pragma unroll
        for (int b = 0; b < 4; b++)
            #pragma unroll
            for (int c = 0; c < 4; c++) acc[a][b][c] = 0.0f;

    const int nk = K / HBK;
    for (int kt = 0; kt < nk; kt++) {
        asm volatile("cp.async.wait_group 1;");
        __syncthreads();

        if (kt + 2 < nk) load_stage(kt + 2, (kt + 2) % 3);
        else             asm volatile("cp.async.commit_group;");

        const uint32_t st = smem_base + (uint32_t)((kt % 3) * STAGE_HALVES) * 2u;
        const uint32_t aa = st + a_lane;
        const uint32_t bb = st + BM * HKP * 2u + b_lane;

        #pragma unroll
        for (int ks = 0; ks < 4; ks++) {
            const uint32_t k0b = (uint32_t)(ks * 32);
            uint32_t af[4][4], bf[2][4];
            #pragma unroll
            for (int mt = 0; mt < 4; mt++)
                ldsm_x4(af[mt], aa + (uint32_t)(mt * 16 * HKP * 2) + k0b);
            ldsm_x4(bf[0], bb + k0b);
            ldsm_x4(bf[1], bb + (uint32_t)(16 * HKP * 2) + k0b);
            #pragma unroll
            for (int mt = 0; mt < 4; mt++) {
                mma_f16(acc[mt][0], af[mt], &bf[0][0]);
                mma_f16(acc[mt][1], af[mt], &bf[0][2]);
                mma_f16(acc[mt][2], af[mt], &bf[1][0]);
                mma_f16(acc[mt][3], af[mt], &bf[1][2]);
            }
        }
    }
    __syncthreads();

    if (OUT_HALF) {
        __half* C = (__half*)Cv;
        #pragma unroll
        for (int mt = 0; mt < 4; mt++) {
            #pragma unroll
            for (int nt = 0; nt < 4; nt++) {
                const int row = m0 + wm * 64 + mt * 16 + lq;
                const int col = n0 + wn * 32 + nt * 8 + lr * 2;
                float x0 = acc[mt][nt][0], x1 = acc[mt][nt][1];
                float x2 = acc[mt][nt][2], x3 = acc[mt][nt][3];
                if (DO_CLIP) {
                    x0 = fminf(fmaxf(x0, -CLIP_V), CLIP_V);
                    x1 = fminf(fmaxf(x1, -CLIP_V), CLIP_V);
                    x2 = fminf(fmaxf(x2, -CLIP_V), CLIP_V);
                    x3 = fminf(fmaxf(x3, -CLIP_V), CLIP_V);
                }
                *(half2*)(C + (size_t)row * N + col)       = __floats2half2_rn(x0, x1);
                *(half2*)(C + (size_t)(row + 8) * N + col) = __floats2half2_rn(x2, x3);
            }
        }
    } else {
        float* C  = (float*)Cv;
        float* ep = (float*)smc + wid * (64 * EP_PITCH);
        #pragma unroll
        for (int mt = 0; mt < 4; mt++) {
            __syncwarp();
            #pragma unroll
            for (int nt = 0; nt < 4; nt++) {
                float* p0 = ep + (lq)     * EP_PITCH + nt * 8 + lr * 2;
                float* p1 = ep + (lq + 8) * EP_PITCH + nt * 8 + lr * 2;
                p0[0] = acc[mt][nt][0]; p0[1] = acc[mt][nt][1];
                p1[0] = acc[mt][nt][2]; p1[1] = acc[mt][nt][3];
            }
            __syncwarp();
            #pragma unroll
            for (int rr = 0; rr < 4; rr++) {
                const int row = rr * 4 + (ln >> 3);
                const int c4  = (ln & 7) * 4;
                float4 v = *(float4*)&ep[row * EP_PITCH + c4];
                *(float4*)(C + (size_t)(m0 + wm * 64 + mt * 16 + row) * N
                             + n0 + wn * 32 + c4) = v;
            }
        }
    }
}

// ---------------------------------------------------------------------------
// RoPE + layout — sincos hoisted to smem (computed once per token block)
// ---------------------------------------------------------------------------
__global__ __launch_bounds__(256)
void rope_kernel()
{
    __shared__ float cs[64], sn[64];

    const int token = blockIdx.x;
    const int b    = token / SEQ;
    const int spos = token - b * SEQ;
    const __half* row = g_qkv + (size_t)token * QKV_N;

    if (threadIdx.x < 64) {
        const int j = threadIdx.x;
        const float freq = __powf(500000.0f, -(float)j * (1.0f / 64.0f));
        sincosf((float)spos * freq, &sn[j], &cs[j]);
    }
    __syncthreads();

    for (int idx = threadIdx.x; idx < (NHEADS + KVHEADS) * 64; idx += 256) {
        const int h = idx >> 6;
        const int j = idx & 63;
        const float s = sn[j], c = cs[j];

        const float x1 = __half2float(row[h * HEADDIM + j]);
        const float x2 = __half2float(row[h * HEADDIM + 64 + j]);
        const float y1 = x1 * c - x2 * s;
        const float y2 = x2 * c + x1 * s;

        if (h < NHEADS) {
            __half* q = g_q + ((size_t)(b * NHEADS + h) * SEQ + spos) * HEADDIM;
            q[j]      = __float2half_rn(y1 * INV_SQRT_D);
            q[j + 64] = __float2half_rn(y2 * INV_SQRT_D);
        } else {
            __half* k = g_k + ((size_t)(b * KVHEADS + (h - NHEADS)) * SEQ + spos) * HEADDIM;
            k[j]      = __float2half_rn(y1);
            k[j + 64] = __float2half_rn(y2);
        }
    }

    const __half* vrow = row + DMODEL + KVHEADS * HEADDIM;
    for (int idx = threadIdx.x; idx < KVHEADS * HEADDIM; idx += 256) {
        const int hk = idx >> 7;
        const int d  = idx & 127;
        g_vt[((size_t)(b * KVHEADS + hk) * HEADDIM + d) * SEQ + spos] = vrow[hk * HEADDIM + d];
    }
}

// ---------------------------------------------------------------------------
// FP16 tensor-core causal flash attention (R11 math; flattened grid so the
// heaviest q-tiles across ALL (h,b) launch in the first wave)
// ---------------------------------------------------------------------------
#define AK_PITCH 136
#define AV_PITCH 72
#define AP_PITCH 72
#define AK_BYTES (64 * AK_PITCH * 2)
#define AV_BYTES (128 * AV_PITCH * 2)
#define AP_BYTES (128 * AP_PITCH * 2)
#define ATTN_SMEM_BYTES (2 * AK_BYTES + 2 * AV_BYTES + AP_BYTES)  // 90,112
#define NQT (SEQ / 128)                                           // 16

__global__ __launch_bounds__(256, 1)
void attn_kernel()
{
    extern __shared__ char smc[];
    const uint32_t smem_base = (uint32_t)__cvta_generic_to_shared(smc);
    const uint32_t kb[2] = { smem_base, smem_base + AK_BYTES };
    const uint32_t vb[2] = { smem_base + 2 * AK_BYTES,
                             smem_base + 2 * AK_BYTES + AV_BYTES };
    const uint32_t ps_base = smem_base + 2 * AK_BYTES + 2 * AV_BYTES;
    __half* Ph = (__half*)(smc + 2 * AK_BYTES + 2 * AV_BYTES);

    // flattened: blockIdx.x in [0, NQT*NHEADS); qtile-major reversed so all
    // (h) of the heaviest qtile go first.
    const int qtile = (NQT - 1) - (blockIdx.x / NHEADS);
    const int h     = blockIdx.x % NHEADS;
    const int b     = blockIdx.y;
    const int hk = h >> 2;
    const int q0 = qtile * 128;
    const int nj = 2 * qtile + 2;

    const int tid = threadIdx.x;
    const int ln  = tid & 31;
    const int wid = tid >> 5;
    const int lq  = ln >> 2;
    const int lr  = ln & 3;

    const uint32_t a_lane_k = (uint32_t)(((wid * 16 + (ln & 15)) * AK_PITCH
                                          + (ln >> 4) * 8) * 2);
    const uint32_t a_lane_p = (uint32_t)(((wid * 16 + (ln & 15)) * AP_PITCH
                                          + (ln >> 4) * 8) * 2);
    const uint32_t b_lane_k = (uint32_t)((((ln >> 4) * 8 + (ln & 7)) * AK_PITCH
                                          + ((ln >> 3) & 1) * 8) * 2);
    const uint32_t b_lane_v = (uint32_t)((((ln >> 4) * 8 + (ln & 7)) * AV_PITCH
                                          + ((ln >> 3) & 1) * 8) * 2);

    const __half* Qg = g_q  + ((size_t)(b * NHEADS  + h)  * SEQ + q0) * HEADDIM;
    const __half* Kg = g_k  + ((size_t)(b * KVHEADS + hk) * SEQ) * HEADDIM;
    const __half* Vg = g_vt + ((size_t)(b * KVHEADS + hk) * HEADDIM) * SEQ;

    auto load_k = [&](int jt) {
        const int j0 = jt * 64;
        const uint32_t base = kb[jt & 1];
        for (int i = tid; i < 1024; i += 256) {
            const int r  = i >> 4;
            const int c8 = (i & 15) << 3;
            cp16(base + (uint32_t)(r * AK_PITCH + c8) * 2u,
                 Kg + (size_t)(j0 + r) * HEADDIM + c8);
        }
        asm volatile("cp.async.commit_group;");
    };
    auto load_v = [&](int jt) {
        const int j0 = jt * 64;
        const uint32_t base = vb[jt & 1];
        for (int i = tid; i < 1024; i += 256) {
            const int r  = i >> 3;
            const int c8 = (i & 7) << 3;
            cp16(base + (uint32_t)(r * AV_PITCH + c8) * 2u,
                 Vg + (size_t)r * SEQ + j0 + c8);
        }
        asm volatile("cp.async.commit_group;");
    };

    for (int i = tid; i < 2048; i += 256) {
        const int r  = i >> 4;
        const int c8 = (i & 15) << 3;
        cp16(kb[0] + (uint32_t)(r * AK_PITCH + c8) * 2u, Qg + (size_t)r * HEADDIM + c8);
    }
    asm volatile("cp.async.commit_group;");
    asm volatile("cp.async.wait_group 0;");
    __syncthreads();

    uint32_t qf[8][4];
    #pragma unroll
    for (int ks = 0; ks < 8; ks++)
        ldsm_x4(qf[ks], kb[0] + a_lane_k + (uint32_t)(ks * 32));
    __syncthreads();

    load_k(0);
    load_v(0);

    float m0 = -3.0e38f, m1 = -3.0e38f, l0 = 0.0f, l1 = 0.0f;
    float o[16][4];
    #pragma unroll
    for (int nt = 0; nt < 16; nt++)
        #pragma unroll
        for (int c = 0; c < 4; c++) o[nt][c] = 0.0f;

    for (int jt = 0; jt < nj; jt++) {
        asm volatile("cp.async.wait_group 1;");
        __syncthreads();

        float s_[8][4];
        #pragma unroll
        for (int t = 0; t < 8; t++)
            #pragma unroll
            for (int c = 0; c < 4; c++) s_[t][c] = 0.0f;

        const uint32_t kbase = kb[jt & 1] + b_lane_k;
        #pragma unroll
        for (int ks = 0; ks < 8; ks++) {
            const uint32_t k0b = (uint32_t)(ks * 32);
            #pragma unroll
            for (int p = 0; p < 4; p++) {
                uint32_t bt[4];
                ldsm_x4(bt, kbase + (uint32_t)(p * 16 * AK_PITCH * 2) + k0b);
                mma_f16(s_[2 * p],     qf[ks], &bt[0]);
                mma_f16(s_[2 * p + 1], qf[ks], &bt[2]);
            }
        }

        if (jt + 1 < nj) load_k(jt + 1);
        else             asm volatile("cp.async.commit_group;");

        if (jt >= nj - 2) {
            const int rrel  = wid * 16 + lq;
            const int crel0 = (jt - (nj - 2)) * 64;
            #pragma unroll
            for (int t = 0; t < 8; t++) {
                const int c0 = crel0 + t * 8 + 2 * lr;
                if (c0     > rrel)     s_[t][0] = -3.0e38f;
                if (c0 + 1 > rrel)     s_[t][1] = -3.0e38f;
                if (c0     > rrel + 8) s_[t][2] = -3.0e38f;
                if (c0 + 1 > rrel + 8) s_[t][3] = -3.0e38f;
            }
        }

        float mx0 = -3.0e38f, mx1 = -3.0e38f;
        #pragma unroll
        for (int t = 0; t < 8; t++) {
            mx0 = fmaxf(mx0, fmaxf(s_[t][0], s_[t][1]));
            mx1 = fmaxf(mx1, fmaxf(s_[t][2], s_[t][3]));
        }
        mx0 = fmaxf(mx0, __shfl_xor_sync(0xffffffffu, mx0, 1));
        mx0 = fmaxf(mx0, __shfl_xor_sync(0xffffffffu, mx0, 2));
        mx1 = fmaxf(mx1, __shfl_xor_sync(0xffffffffu, mx1, 1));
        mx1 = fmaxf(mx1, __shfl_xor_sync(0xffffffffu, mx1, 2));

        const float mn0 = fmaxf(m0, mx0);
        const float mn1 = fmaxf(m1, mx1);
        const float al0 = __expf(m0 - mn0);
        const float al1 = __expf(m1 - mn1);
        float rs0 = 0.0f, rs1 = 0.0f;
        #pragma unroll
        for (int t = 0; t < 8; t++) {
            s_[t][0] = __expf(s_[t][0] - mn0); rs0 += s_[t][0];
            s_[t][1] = __expf(s_[t][1] - mn0); rs0 += s_[t][1];
            s_[t][2] = __expf(s_[t][2] - mn1); rs1 += s_[t][2];
            s_[t][3] = __expf(s_[t][3] - mn1); rs1 += s_[t][3];
        }
        rs0 += __shfl_xor_sync(0xffffffffu, rs0, 1);
        rs0 += __shfl_xor_sync(0xffffffffu, rs0, 2);
        rs1 += __shfl_xor_sync(0xffffffffu, rs1, 1);
        rs1 += __shfl_xor_sync(0xffffffffu, rs1, 2);
        l0 = l0 * al0 + rs0;  m0 = mn0;
        l1 = l1 * al1 + rs1;  m1 = mn1;
        #pragma unroll
        for (int nt = 0; nt < 16; nt++) {
            o[nt][0] *= al0; o[nt][1] *= al0;
            o[nt][2] *= al1; o[nt][3] *= al1;
        }

        asm volatile("cp.async.wait_group 1;");

        {
            __half* p0 = Ph + (wid * 16 + lq) * AP_PITCH + 2 * lr;
            __half* p1 = p0 + 8 * AP_PITCH;
            #pragma unroll
            for (int t = 0; t < 8; t++) {
                *(half2*)(p0 + t * 8) = __floats2half2_rn(s_[t][0], s_[t][1]);
                *(half2*)(p1 + t * 8) = __floats2half2_rn(s_[t][2], s_[t][3]);
            }
        }
        __syncwarp();

        const uint32_t vbase = vb[jt & 1] + b_lane_v;
        #pragma unroll
        for (int ks = 0; ks < 4; ks++) {
            const uint32_t k0b = (uint32_t)(ks * 32);
            uint32_t a[4];
            ldsm_x4(a, ps_base + a_lane_p + k0b);
            #pragma unroll
            for (int p = 0; p < 8; p++) {
                uint32_t bt[4];
                ldsm_x4(bt, vbase + (uint32_t)(p * 16 * AV_PITCH * 2) + k0b);
                mma_f16(o[2 * p],     a, &bt[0]);
                mma_f16(o[2 * p + 1], a, &bt[2]);
            }
        }

        if (jt + 1 < nj) load_v(jt + 1);
        else             asm volatile("cp.async.commit_group;");
    }

    const float inv0 = 1.0f / l0;
    const float inv1 = 1.0f / l1;
    const int s0 = q0 + wid * 16 + lq;
    __half* O0 = g_attn + (size_t)(b * SEQ + s0) * DMODEL + h * HEADDIM + 2 * lr;
    __half* O1 = O0 + (size_t)8 * DMODEL;
    #pragma unroll
    for (int nt = 0; nt < 16; nt++) {
        *(half2*)(O0 + nt * 8) = __floats2half2_rn(o[nt][0] * inv0, o[nt][1] * inv0);
        *(half2*)(O1 + nt * 8) = __floats2half2_rn(o[nt][2] * inv1, o[nt][3] * inv1);
    }
}

// ---------------------------------------------------------------------------
// Launch sequence
// ---------------------------------------------------------------------------
extern "C" void kernel_launch(void* const* d_in, const int* in_sizes, int n_in,
                              void* d_out, int out_size)
{
    const float* hidden = (const float*)d_in[0];
    const float* Wqkv   = (const float*)d_in[3];
    const float* out_w  = (const float*)d_in[4];
    float*       out    = (float*)d_out;

    __half *qkv_p, *attn_p, *hid_p, *wq_p, *wo_p;
    cudaGetSymbolAddress((void**)&qkv_p,  g_qkv);
    cudaGetSymbolAddress((void**)&attn_p, g_attn);
    cudaGetSymbolAddress((void**)&hid_p,  g_hid);
    cudaGetSymbolAddress((void**)&wq_p,   g_wq);
    cudaGetSymbolAddress((void**)&wo_p,   g_wo);

    cudaFuncSetAttribute((const void*)gemm_f16<true, true>,
                         cudaFuncAttributeMaxDynamicSharedMemorySize, GEMM_SMEM_BYTES);
    cudaFuncSetAttribute((const void*)gemm_f16<false, false>,
                         cudaFuncAttributeMaxDynamicSharedMemorySize, GEMM_SMEM_BYTES);
    cudaFuncSetAttribute((const void*)attn_kernel,
                         cudaFuncAttributeMaxDynamicSharedMemorySize, ATTN_SMEM_BYTES);

    // 0) fused fp16 pre-round (one launch)
    round_all_kernel<<<1184, 256>>>((const float4*)hidden, (const float4*)Wqkv,
                                    (const float4*)out_w,
                                    (half2*)hid_p, (half2*)wq_p, (half2*)wo_p);

    // 1) QKV projection with clip (half output)
    gemm_f16<true, true><<<dim3(QKV_N / BN, TOKENS / BM), 256, GEMM_SMEM_BYTES>>>(
        hid_p, wq_p, qkv_p, TOKENS, QKV_N, DMODEL);

    // 2) RoPE + layouts
    rope_kernel<<<TOKENS, 256>>>();

    // 3) fp16 tensor-core causal flash attention
    attn_kernel<<<dim3(NQT * NHEADS, BATCH), 256, ATTN_SMEM_BYTES>>>();

    // 4) output projection (f32 output)
    gemm_f16<false, false><<<dim3(DMODEL / BN, TOKENS / BM), 256, GEMM_SMEM_BYTES>>>(
        attn_p, wo_p, out, TOKENS, DMODEL, DMODEL);
}

// round 16
// speedup vs baseline: 1.0713x; 1.0237x over previous
#include <cuda_runtime.h>
#include <cuda_fp16.h>
#include <math.h>
#include <stdint.h>

// ---------------------------------------------------------------------------
// Problem constants
// ---------------------------------------------------------------------------
#define BATCH     2
#define SEQ       2048
#define DMODEL    4096
#define NHEADS    32
#define KVHEADS   8
#define HEADDIM   128
#define QKV_N     (DMODEL + 2 * KVHEADS * HEADDIM)   // 6144
#define TOKENS    (BATCH * SEQ)                      // 4096
#define CLIP_V    8.0f
#define INV_SQRT_D 0.08838834764831845f

// ---------------------------------------------------------------------------
// Scratch (device globals) — fp16 operands
// ---------------------------------------------------------------------------
__device__ __half g_qkv [(size_t)TOKENS * QKV_N];
__device__ __half g_q   [(size_t)BATCH * NHEADS  * SEQ * HEADDIM];
__device__ __half g_k   [(size_t)BATCH * KVHEADS * SEQ * HEADDIM];
__device__ __half g_vt  [(size_t)BATCH * KVHEADS * HEADDIM * SEQ];
__device__ __half g_attn[(size_t)TOKENS * DMODEL];
__device__ __half g_hid [(size_t)TOKENS * DMODEL];
__device__ __half g_wq  [(size_t)QKV_N  * DMODEL];
__device__ __half g_wo  [(size_t)DMODEL * DMODEL];

// ---------------------------------------------------------------------------
// helpers
// ---------------------------------------------------------------------------
__device__ __forceinline__ void mma_f16(float* c, const uint32_t* a, const uint32_t* b) {
    asm volatile(
        "mma.sync.aligned.m16n8k16.row.col.f32.f16.f16.f32 "
        "{%0,%1,%2,%3}, {%4,%5,%6,%7}, {%8,%9}, {%0,%1,%2,%3};"
        : "+f"(c[0]), "+f"(c[1]), "+f"(c[2]), "+f"(c[3])
        : "r"(a[0]), "r"(a[1]), "r"(a[2]), "r"(a[3]), "r"(b[0]), "r"(b[1]));
}
__device__ __forceinline__ void cp16(uint32_t s, const void* g) {
    asm volatile("cp.async.cg.shared.global [%0], [%1], 16;" :: "r"(s), "l"(g));
}
__device__ __forceinline__ void ldsm_x4(uint32_t* r, uint32_t addr) {
    asm volatile("ldmatrix.sync.aligned.m8n8.x4.shared.b16 {%0,%1,%2,%3}, [%4];"
                 : "=r"(r[0]), "=r"(r[1]), "=r"(r[2]), "=r"(r[3]) : "r"(addr));
}

// ---------------------------------------------------------------------------
// fused f32 -> fp16 round of hidden + Wqkv + out_w in ONE launch
// ---------------------------------------------------------------------------
#define N4_HID (TOKENS * DMODEL / 4)
#define N4_WQ  (QKV_N  * DMODEL / 4)
#define N4_WO  (DMODEL * DMODEL / 4)
#define N4_ALL (N4_HID + N4_WQ + N4_WO)

__global__ __launch_bounds__(256)
void round_all_kernel(const float4* __restrict__ hid, const float4* __restrict__ wq,
                      const float4* __restrict__ wo,
                      half2* __restrict__ hid_o, half2* __restrict__ wq_o,
                      half2* __restrict__ wo_o)
{
    for (int i = blockIdx.x * blockDim.x + threadIdx.x; i < N4_ALL;
         i += gridDim.x * blockDim.x) {
        const float4* src;
        half2* dst;
        int j = i;
        if (j < N4_HID)            { src = hid; dst = hid_o; }
        else if ((j -= N4_HID) < N4_WQ) { src = wq; dst = wq_o; }
        else { j -= N4_WQ;           src = wo;  dst = wo_o; }
        float4 v = src[j];
        dst[2 * j]     = __floats2half2_rn(v.x, v.y);
        dst[2 * j + 1] = __floats2half2_rn(v.z, v.w);
    }
}

// ---------------------------------------------------------------------------
// FP16 tensor-core GEMM (R11/R13 config — best measured)
// ---------------------------------------------------------------------------
#define BM 128
#define BN 128
#define HBK 64
#define HKP 72
#define STAGE_HALVES (BM * HKP + BN * HKP)            // 18,432 halves
#define GEMM_SMEM_BYTES (3 * STAGE_HALVES * 2)        // 110,592
#define EP_PITCH 36

template <bool DO_CLIP, bool OUT_HALF>
__global__ __launch_bounds__(256, 2)
void gemm_f16(const __half* __restrict__ A, const __half* __restrict__ B,
              void* __restrict__ Cv, int M, int N, int K)
{
    extern __shared__ char smc[];
    const uint32_t smem_base = (uint32_t)__cvta_generic_to_shared(smc);

    const int tid = threadIdx.x;
    const int ln  = tid & 31;
    const int wid = tid >> 5;
    const int wm  = wid >> 2;
    const int wn  = wid & 3;
    const int m0  = blockIdx.y * BM;
    const int n0  = blockIdx.x * BN;
    const int lq  = ln >> 2;
    const int lr  = ln & 3;

    const uint32_t a_lane = (uint32_t)(((wm * 64 + (ln & 15)) * HKP + (ln >> 4) * 8) * 2);
    const uint32_t b_lane = (uint32_t)(((wn * 32 + (ln >> 4) * 8 + (ln & 7)) * HKP
                                        + ((ln >> 3) & 1) * 8) * 2);

    const __half* Abase = A + (size_t)m0 * K;
    const __half* Bbase = B + (size_t)n0 * K;

    auto load_stage = [&](int kt, int s) {
        const __half* Ag = Abase + kt * HBK;
        const __half* Bg = Bbase + kt * HBK;
        const uint32_t sa = smem_base + (uint32_t)(s * STAGE_HALVES) * 2u;
        const uint32_t sb = sa + BM * HKP * 2u;
        #pragma unroll
        for (int r = 0; r < 4; r++) {
            const int i   = r * 256 + tid;
            const int row = i >> 3;
            const int kc  = (i & 7) << 3;
            cp16(sa + (uint32_t)(row * HKP + kc) * 2u, Ag + (size_t)row * K + kc);
            cp16(sb + (uint32_t)(row * HKP + kc) * 2u, Bg + (size_t)row * K + kc);
        }
        asm volatile("cp.async.commit_group;");
    };

    load_stage(0, 0);
    load_stage(1, 1);

    float acc[4][4][4];
    #pragma unroll
    for (int a = 0; a < 4; a++)
        #pragma unroll
        for (int b = 0; b < 4; b++)
            #pragma unroll
            for (int c = 0; c < 4; c++) acc[a][b][c] = 0.0f;

    const int nk = K / HBK;
    for (int kt = 0; kt < nk; kt++) {
        asm volatile("cp.async.wait_group 1;");
        __syncthreads();

        if (kt + 2 < nk) load_stage(kt + 2, (kt + 2) % 3);
        else             asm volatile("cp.async.commit_group;");

        const uint32_t st = smem_base + (uint32_t)((kt % 3) * STAGE_HALVES) * 2u;
        const uint32_t aa = st + a_lane;
        const uint32_t bb = st + BM * HKP * 2u + b_lane;

        #pragma unroll
        for (int ks = 0; ks < 4; ks++) {
            const uint32_t k0b = (uint32_t)(ks * 32);
            uint32_t af[4][4], bf[2][4];
            #pragma unroll
            for (int mt = 0; mt < 4; mt++)
                ldsm_x4(af[mt], aa + (uint32_t)(mt * 16 * HKP * 2) + k0b);
            ldsm_x4(bf[0], bb + k0b);
            ldsm_x4(bf[1], bb + (uint32_t)(16 * HKP * 2) + k0b);
            #pragma unroll
            for (int mt = 0; mt < 4; mt++) {
                mma_f16(acc[mt][0], af[mt], &bf[0][0]);
                mma_f16(acc[mt][1], af[mt], &bf[0][2]);
                mma_f16(acc[mt][2], af[mt], &bf[1][0]);
                mma_f16(acc[mt][3], af[mt], &bf[1][2]);
            }
        }
    }
    __syncthreads();

    if (OUT_HALF) {
        __half* C = (__half*)Cv;
        #pragma unroll
        for (int mt = 0; mt < 4; mt++) {
            #pragma unroll
            for (int nt = 0; nt < 4; nt++) {
                const int row = m0 + wm * 64 + mt * 16 + lq;
                const int col = n0 + wn * 32 + nt * 8 + lr * 2;
                float x0 = acc[mt][nt][0], x1 = acc[mt][nt][1];
                float x2 = acc[mt][nt][2], x3 = acc[mt][nt][3];
                if (DO_CLIP) {
                    x0 = fminf(fmaxf(x0, -CLIP_V), CLIP_V);
                    x1 = fminf(fmaxf(x1, -CLIP_V), CLIP_V);
                    x2 = fminf(fmaxf(x2, -CLIP_V), CLIP_V);
                    x3 = fminf(fmaxf(x3, -CLIP_V), CLIP_V);
                }
                *(half2*)(C + (size_t)row * N + col)       = __floats2half2_rn(x0, x1);
                *(half2*)(C + (size_t)(row + 8) * N + col) = __floats2half2_rn(x2, x3);
            }
        }
    } else {
        float* C  = (float*)Cv;
        float* ep = (float*)smc + wid * (64 * EP_PITCH);
        #pragma unroll
        for (int mt = 0; mt < 4; mt++) {
            __syncwarp();
            #pragma unroll
            for (int nt = 0; nt < 4; nt++) {
                float* p0 = ep + (lq)     * EP_PITCH + nt * 8 + lr * 2;
                float* p1 = ep + (lq + 8) * EP_PITCH + nt * 8 + lr * 2;
                p0[0] = acc[mt][nt][0]; p0[1] = acc[mt][nt][1];
                p1[0] = acc[mt][nt][2]; p1[1] = acc[mt][nt][3];
            }
            __syncwarp();
            #pragma unroll
            for (int rr = 0; rr < 4; rr++) {
                const int row = rr * 4 + (ln >> 3);
                const int c4  = (ln & 7) * 4;
                float4 v = *(float4*)&ep[row * EP_PITCH + c4];
                *(float4*)(C + (size_t)(m0 + wm * 64 + mt * 16 + row) * N
                             + n0 + wn * 32 + c4) = v;
            }
        }
    }
}

// ---------------------------------------------------------------------------
// RoPE + layout — sincos hoisted to smem
// ---------------------------------------------------------------------------
__global__ __launch_bounds__(256)
void rope_kernel()
{
    __shared__ float cs[64], sn[64];

    const int token = blockIdx.x;
    const int b    = token / SEQ;
    const int spos = token - b * SEQ;
    const __half* row = g_qkv + (size_t)token * QKV_N;

    if (threadIdx.x < 64) {
        const int j = threadIdx.x;
        const float freq = __powf(500000.0f, -(float)j * (1.0f / 64.0f));
        sincosf((float)spos * freq, &sn[j], &cs[j]);
    }
    __syncthreads();

    for (int idx = threadIdx.x; idx < (NHEADS + KVHEADS) * 64; idx += 256) {
        const int h = idx >> 6;
        const int j = idx & 63;
        const float s = sn[j], c = cs[j];

        const float x1 = __half2float(row[h * HEADDIM + j]);
        const float x2 = __half2float(row[h * HEADDIM + 64 + j]);
        const float y1 = x1 * c - x2 * s;
        const float y2 = x2 * c + x1 * s;

        if (h < NHEADS) {
            __half* q = g_q + ((size_t)(b * NHEADS + h) * SEQ + spos) * HEADDIM;
            q[j]      = __float2half_rn(y1 * INV_SQRT_D);
            q[j + 64] = __float2half_rn(y2 * INV_SQRT_D);
        } else {
            __half* k = g_k + ((size_t)(b * KVHEADS + (h - NHEADS)) * SEQ + spos) * HEADDIM;
            k[j]      = __float2half_rn(y1);
            k[j + 64] = __float2half_rn(y2);
        }
    }

    const __half* vrow = row + DMODEL + KVHEADS * HEADDIM;
    for (int idx = threadIdx.x; idx < KVHEADS * HEADDIM; idx += 256) {
        const int hk = idx >> 7;
        const int d  = idx & 127;
        g_vt[((size_t)(b * KVHEADS + hk) * HEADDIM + d) * SEQ + spos] = vrow[hk * HEADDIM + d];
    }
}

// ---------------------------------------------------------------------------
// FP16 causal flash attention — 2 CTAs/SM version.
// Q persistent in smem (fragments re-ldsm'd per iter -> regs <= 128),
// K double-buffered, V single-buffered (explicit visibility/drain syncs).
// smem: Q[128][136] + K0,K1[64][136] + V[128][72] + P[128][72] = 106,496 B.
// ---------------------------------------------------------------------------
#define AK_PITCH 136
#define AV_PITCH 72
#define AP_PITCH 72
#define QB_BYTES (128 * AK_PITCH * 2)   // 34,816
#define AK_BYTES (64 * AK_PITCH * 2)    // 17,408
#define AV_BYTES (128 * AV_PITCH * 2)   // 18,432
#define AP_BYTES (128 * AP_PITCH * 2)   // 18,432
#define ATTN_SMEM_BYTES (QB_BYTES + 2 * AK_BYTES + AV_BYTES + AP_BYTES) // 106,496
#define NQT (SEQ / 128)                 // 16

__global__ __launch_bounds__(256, 2)
void attn_kernel()
{
    extern __shared__ char smc[];
    const uint32_t smem_base = (uint32_t)__cvta_generic_to_shared(smc);
    const uint32_t qb      = smem_base;
    const uint32_t kb[2]   = { smem_base + QB_BYTES,
                               smem_base + QB_BYTES + AK_BYTES };
    const uint32_t vbs     = smem_base + QB_BYTES + 2 * AK_BYTES;
    const uint32_t ps_base = vbs + AV_BYTES;
    __half* Ph = (__half*)(smc + QB_BYTES + 2 * AK_BYTES + AV_BYTES);

    const int qtile = (NQT - 1) - (blockIdx.x / NHEADS);
    const int h     = blockIdx.x % NHEADS;
    const int b     = blockIdx.y;
    const int hk = h >> 2;
    const int q0 = qtile * 128;
    const int nj = 2 * qtile + 2;

    const int tid = threadIdx.x;
    const int ln  = tid & 31;
    const int wid = tid >> 5;
    const int lq  = ln >> 2;
    const int lr  = ln & 3;

    const uint32_t a_lane_q = (uint32_t)(((wid * 16 + (ln & 15)) * AK_PITCH
                                          + (ln >> 4) * 8) * 2);
    const uint32_t a_lane_p = (uint32_t)(((wid * 16 + (ln & 15)) * AP_PITCH
                                          + (ln >> 4) * 8) * 2);
    const uint32_t b_lane_k = (uint32_t)((((ln >> 4) * 8 + (ln & 7)) * AK_PITCH
                                          + ((ln >> 3) & 1) * 8) * 2);
    const uint32_t b_lane_v = (uint32_t)((((ln >> 4) * 8 + (ln & 7)) * AV_PITCH
                                          + ((ln >> 3) & 1) * 8) * 2);

    const __half* Qg = g_q  + ((size_t)(b * NHEADS  + h)  * SEQ + q0) * HEADDIM;
    const __half* Kg = g_k  + ((size_t)(b * KVHEADS + hk) * SEQ) * HEADDIM;
    const __half* Vg = g_vt + ((size_t)(b * KVHEADS + hk) * HEADDIM) * SEQ;

    auto load_k = [&](int jt) {
        const int j0 = jt * 64;
        const uint32_t base = kb[jt & 1];
        for (int i = tid; i < 1024; i += 256) {
            const int r  = i >> 4;
            const int c8 = (i & 15) << 3;
            cp16(base + (uint32_t)(r * AK_PITCH + c8) * 2u,
                 Kg + (size_t)(j0 + r) * HEADDIM + c8);
        }
        asm volatile("cp.async.commit_group;");
    };
    auto load_v = [&](int jt) {
        const int j0 = jt * 64;
        for (int i = tid; i < 1024; i += 256) {
            const int r  = i >> 3;
            const int c8 = (i & 7) << 3;
            cp16(vbs + (uint32_t)(r * AV_PITCH + c8) * 2u,
                 Vg + (size_t)r * SEQ + j0 + c8);
        }
        asm volatile("cp.async.commit_group;");
    };

    // ---- prologue: Q into its persistent buffer ----
    for (int i = tid; i < 2048; i += 256) {
        const int r  = i >> 4;
        const int c8 = (i & 15) << 3;
        cp16(qb + (uint32_t)(r * AK_PITCH + c8) * 2u, Qg + (size_t)r * HEADDIM + c8);
    }
    asm volatile("cp.async.commit_group;");
    asm volatile("cp.async.wait_group 0;");
    __syncthreads();

    load_k(0);
    load_v(0);

    float m0 = -3.0e38f, m1 = -3.0e38f, l0 = 0.0f, l1 = 0.0f;
    float o[16][4];
    #pragma unroll
    for (int nt = 0; nt < 16; nt++)
        #pragma unroll
        for (int c = 0; c < 4; c++) o[nt][c] = 0.0f;

    for (int jt = 0; jt < nj; jt++) {
        asm volatile("cp.async.wait_group 1;");   // K(jt) done (V(jt) may pend)
        __syncthreads();                          // K visible; K buf reuse safe

        // ---- S = Q K^T (Q fragments re-ldsm'd from persistent buffer) ----
        float s_[8][4];
        #pragma unroll
        for (int t = 0; t < 8; t++)
            #pragma unroll
            for (int c = 0; c < 4; c++) s_[t][c] = 0.0f;

        const uint32_t kbase = kb[jt & 1] + b_lane_k;
        #pragma unroll
        for (int ks = 0; ks < 8; ks++) {
            const uint32_t k0b = (uint32_t)(ks * 32);
            uint32_t qf[4];
            ldsm_x4(qf, qb + a_lane_q + k0b);
            #pragma unroll
            for (int p = 0; p < 4; p++) {
                uint32_t bt[4];
                ldsm_x4(bt, kbase + (uint32_t)(p * 16 * AK_PITCH * 2) + k0b);
                mma_f16(s_[2 * p],     qf, &bt[0]);
                mma_f16(s_[2 * p + 1], qf, &bt[2]);
            }
        }

        if (jt + 1 < nj) load_k(jt + 1);
        else             asm volatile("cp.async.commit_group;");

        if (jt >= nj - 2) {                       // causal mask (last two tiles)
            const int rrel  = wid * 16 + lq;
            const int crel0 = (jt - (nj - 2)) * 64;
            #pragma unroll
            for (int t = 0; t < 8; t++) {
                const int c0 = crel0 + t * 8 + 2 * lr;
                if (c0     > rrel)     s_[t][0] = -3.0e38f;
                if (c0 + 1 > rrel)     s_[t][1] = -3.0e38f;
                if (c0     > rrel + 8) s_[t][2] = -3.0e38f;
                if (c0 + 1 > rrel + 8) s_[t][3] = -3.0e38f;
            }
        }

        // ---- online softmax ----
        float mx0 = -3.0e38f, mx1 = -3.0e38f;
        #pragma unroll
        for (int t = 0; t < 8; t++) {
            mx0 = fmaxf(mx0, fmaxf(s_[t][0], s_[t][1]));
            mx1 = fmaxf(mx1, fmaxf(s_[t][2], s_[t][3]));
        }
        mx0 = fmaxf(mx0, __shfl_xor_sync(0xffffffffu, mx0, 1));
        mx0 = fmaxf(mx0, __shfl_xor_sync(0xffffffffu, mx0, 2));
        mx1 = fmaxf(mx1, __shfl_xor_sync(0xffffffffu, mx1, 1));
        mx1 = fmaxf(mx1, __shfl_xor_sync(0xffffffffu, mx1, 2));

        const float mn0 = fmaxf(m0, mx0);
        const float mn1 = fmaxf(m1, mx1);
        const float al0 = __expf(m0 - mn0);
        const float al1 = __expf(m1 - mn1);
        float rs0 = 0.0f, rs1 = 0.0f;
        #pragma unroll
        for (int t = 0; t < 8; t++) {
            s_[t][0] = __expf(s_[t][0] - mn0); rs0 += s_[t][0];
            s_[t][1] = __expf(s_[t][1] - mn0); rs0 += s_[t][1];
            s_[t][2] = __expf(s_[t][2] - mn1); rs1 += s_[t][2];
            s_[t][3] = __expf(s_[t][3] - mn1); rs1 += s_[t][3];
        }
        rs0 += __shfl_xor_sync(0xffffffffu, rs0, 1);
        rs0 += __shfl_xor_sync(0xffffffffu, rs0, 2);
        rs1 += __shfl_xor_sync(0xffffffffu, rs1, 1);
        rs1 += __shfl_xor_sync(0xffffffffu, rs1, 2);
        l0 = l0 * al0 + rs0;  m0 = mn0;
        l1 = l1 * al1 + rs1;  m1 = mn1;
        #pragma unroll
        for (int nt = 0; nt < 16; nt++) {
            o[nt][0] *= al0; o[nt][1] *= al0;
            o[nt][2] *= al1; o[nt][3] *= al1;
        }

        asm volatile("cp.async.wait_group 1;");   // V(jt) done (K(jt+1) may pend)
        __syncthreads();                          // V visible to all warps

        // ---- store P as half (own rows only) ----
        {
            __half* p0 = Ph + (wid * 16 + lq) * AP_PITCH + 2 * lr;
            __half* p1 = p0 + 8 * AP_PITCH;
            #pragma unroll
            for (int t = 0; t < 8; t++) {
                *(half2*)(p0 + t * 8) = __floats2half2_rn(s_[t][0], s_[t][1]);
                *(half2*)(p1 + t * 8) = __floats2half2_rn(s_[t][2], s_[t][3]);
            }
        }
        __syncwarp();

        // ---- O += P Vt ----
        const uint32_t vbase = vbs + b_lane_v;
        #pragma unroll
        for (int ks = 0; ks < 4; ks++) {
            const uint32_t k0b = (uint32_t)(ks * 32);
            uint32_t a[4];
            ldsm_x4(a, ps_base + a_lane_p + k0b);
            #pragma unroll
            for (int p = 0; p < 8; p++) {
                uint32_t bt[4];
                ldsm_x4(bt, vbase + (uint32_t)(p * 16 * AV_PITCH * 2) + k0b);
                mma_f16(o[2 * p],     a, &bt[0]);
                mma_f16(o[2 * p + 1], a, &bt[2]);
            }
        }

        __syncthreads();                          // all warps done reading V
        if (jt + 1 < nj) load_v(jt + 1);          // hides behind next S+softmax
        else             asm volatile("cp.async.commit_group;");
    }

    // ---- epilogue ----
    const float inv0 = 1.0f / l0;
    const float inv1 = 1.0f / l1;
    const int s0 = q0 + wid * 16 + lq;
    __half* O0 = g_attn + (size_t)(b * SEQ + s0) * DMODEL + h * HEADDIM + 2 * lr;
    __half* O1 = O0 + (size_t)8 * DMODEL;
    #pragma unroll
    for (int nt = 0; nt < 16; nt++) {
        *(half2*)(O0 + nt * 8) = __floats2half2_rn(o[nt][0] * inv0, o[nt][1] * inv0);
        *(half2*)(O1 + nt * 8) = __floats2half2_rn(o[nt][2] * inv1, o[nt][3] * inv1);
    }
}

// ---------------------------------------------------------------------------
// Launch sequence
// ---------------------------------------------------------------------------
extern "C" void kernel_launch(void* const* d_in, const int* in_sizes, int n_in,
                              void* d_out, int out_size)
{
    const float* hidden = (const float*)d_in[0];
    const float* Wqkv   = (const float*)d_in[3];
    const float* out_w  = (const float*)d_in[4];
    float*       out    = (float*)d_out;

    __half *qkv_p, *attn_p, *hid_p, *wq_p, *wo_p;
    cudaGetSymbolAddress((void**)&qkv_p,  g_qkv);
    cudaGetSymbolAddress((void**)&attn_p, g_attn);
    cudaGetSymbolAddress((void**)&hid_p,  g_hid);
    cudaGetSymbolAddress((void**)&wq_p,   g_wq);
    cudaGetSymbolAddress((void**)&wo_p,   g_wo);

    cudaFuncSetAttribute((const void*)gemm_f16<true, true>,
                         cudaFuncAttributeMaxDynamicSharedMemorySize, GEMM_SMEM_BYTES);
    cudaFuncSetAttribute((const void*)gemm_f16<false, false>,
                         cudaFuncAttributeMaxDynamicSharedMemorySize, GEMM_SMEM_BYTES);
    cudaFuncSetAttribute((const void*)attn_kernel,
                         cudaFuncAttributeMaxDynamicSharedMemorySize, ATTN_SMEM_BYTES);

    // 0) fused fp16 pre-round (one launch)
    round_all_kernel<<<1184, 256>>>((const float4*)hidden, (const float4*)Wqkv,
                                    (const float4*)out_w,
                                    (half2*)hid_p, (half2*)wq_p, (half2*)wo_p);

    // 1) QKV projection with clip (half output)
    gemm_f16<true, true><<<dim3(QKV_N / BN, TOKENS / BM), 256, GEMM_SMEM_BYTES>>>(
        hid_p, wq_p, qkv_p, TOKENS, QKV_N, DMODEL);

    // 2) RoPE + layouts
    rope_kernel<<<TOKENS, 256>>>();

    // 3) fp16 causal flash attention (2 CTAs/SM)
    attn_kernel<<<dim3(NQT * NHEADS, BATCH), 256, ATTN_SMEM_BYTES>>>();

    // 4) output projection (f32 output)
    gemm_f16<false, false><<<dim3(DMODEL / BN, TOKENS / BM), 256, GEMM_SMEM_BYTES>>>(
        attn_p, wo_p, out, TOKENS, DMODEL, DMODEL);
}

// round 17
// speedup vs baseline: 1.0875x; 1.0151x over previous
#include <cuda_runtime.h>
#include <cuda_fp16.h>
#include <math.h>
#include <stdint.h>

// ---------------------------------------------------------------------------
// Problem constants
// ---------------------------------------------------------------------------
#define BATCH     2
#define SEQ       2048
#define DMODEL    4096
#define NHEADS    32
#define KVHEADS   8
#define HEADDIM   128
#define QKV_N     (DMODEL + 2 * KVHEADS * HEADDIM)   // 6144
#define TOKENS    (BATCH * SEQ)                      // 4096
#define CLIP_V    8.0f
#define INV_SQRT_D 0.08838834764831845f

// ---------------------------------------------------------------------------
// Scratch (device globals) — fp16 operands
// ---------------------------------------------------------------------------
__device__ __half g_qkv [(size_t)TOKENS * QKV_N];
__device__ __half g_q   [(size_t)BATCH * NHEADS  * SEQ * HEADDIM];
__device__ __half g_k   [(size_t)BATCH * KVHEADS * SEQ * HEADDIM];
__device__ __half g_vt  [(size_t)BATCH * KVHEADS * HEADDIM * SEQ];
__device__ __half g_attn[(size_t)TOKENS * DMODEL];
__device__ __half g_hid [(size_t)TOKENS * DMODEL];
__device__ __half g_wq  [(size_t)QKV_N  * DMODEL];
__device__ __half g_wo  [(size_t)DMODEL * DMODEL];

// ---------------------------------------------------------------------------
// helpers
// ---------------------------------------------------------------------------
__device__ __forceinline__ void mma_f16(float* c, const uint32_t* a, const uint32_t* b) {
    asm volatile(
        "mma.sync.aligned.m16n8k16.row.col.f32.f16.f16.f32 "
        "{%0,%1,%2,%3}, {%4,%5,%6,%7}, {%8,%9}, {%0,%1,%2,%3};"
        : "+f"(c[0]), "+f"(c[1]), "+f"(c[2]), "+f"(c[3])
        : "r"(a[0]), "r"(a[1]), "r"(a[2]), "r"(a[3]), "r"(b[0]), "r"(b[1]));
}
__device__ __forceinline__ void cp16(uint32_t s, const void* g) {
    asm volatile("cp.async.cg.shared.global [%0], [%1], 16;" :: "r"(s), "l"(g));
}
__device__ __forceinline__ void ldsm_x4(uint32_t* r, uint32_t addr) {
    asm volatile("ldmatrix.sync.aligned.m8n8.x4.shared.b16 {%0,%1,%2,%3}, [%4];"
                 : "=r"(r[0]), "=r"(r[1]), "=r"(r[2]), "=r"(r[3]) : "r"(addr));
}
__device__ __forceinline__ uint32_t pkh2(float x, float y) {
    half2 h = __floats2half2_rn(x, y);
    return *(uint32_t*)&h;
}

// ---------------------------------------------------------------------------
// fused f32 -> fp16 round of hidden + Wqkv + out_w in ONE launch
// ---------------------------------------------------------------------------
#define N4_HID (TOKENS * DMODEL / 4)
#define N4_WQ  (QKV_N  * DMODEL / 4)
#define N4_WO  (DMODEL * DMODEL / 4)
#define N4_ALL (N4_HID + N4_WQ + N4_WO)

__global__ __launch_bounds__(256)
void round_all_kernel(const float4* __restrict__ hid, const float4* __restrict__ wq,
                      const float4* __restrict__ wo,
                      half2* __restrict__ hid_o, half2* __restrict__ wq_o,
                      half2* __restrict__ wo_o)
{
    for (int i = blockIdx.x * blockDim.x + threadIdx.x; i < N4_ALL;
         i += gridDim.x * blockDim.x) {
        const float4* src;
        half2* dst;
        int j = i;
        if (j < N4_HID)            { src = hid; dst = hid_o; }
        else if ((j -= N4_HID) < N4_WQ) { src = wq; dst = wq_o; }
        else { j -= N4_WQ;           src = wo;  dst = wo_o; }
        float4 v = src[j];
        dst[2 * j]     = __floats2half2_rn(v.x, v.y);
        dst[2 * j + 1] = __floats2half2_rn(v.z, v.w);
    }
}

// ---------------------------------------------------------------------------
// FP16 tensor-core GEMM (R11/R13 config — best measured)
// ---------------------------------------------------------------------------
#define BM 128
#define BN 128
#define HBK 64
#define HKP 72
#define STAGE_HALVES (BM * HKP + BN * HKP)            // 18,432 halves
#define GEMM_SMEM_BYTES (3 * STAGE_HALVES * 2)        // 110,592
#define EP_PITCH 36

template <bool DO_CLIP, bool OUT_HALF>
__global__ __launch_bounds__(256, 2)
void gemm_f16(const __half* __restrict__ A, const __half* __restrict__ B,
              void* __restrict__ Cv, int M, int N, int K)
{
    extern __shared__ char smc[];
    const uint32_t smem_base = (uint32_t)__cvta_generic_to_shared(smc);

    const int tid = threadIdx.x;
    const int ln  = tid & 31;
    const int wid = tid >> 5;
    const int wm  = wid >> 2;
    const int wn  = wid & 3;
    const int m0  = blockIdx.y * BM;
    const int n0  = blockIdx.x * BN;
    const int lq  = ln >> 2;
    const int lr  = ln & 3;

    const uint32_t a_lane = (uint32_t)(((wm * 64 + (ln & 15)) * HKP + (ln >> 4) * 8) * 2);
    const uint32_t b_lane = (uint32_t)(((wn * 32 + (ln >> 4) * 8 + (ln & 7)) * HKP
                                        + ((ln >> 3) & 1) * 8) * 2);

    const __half* Abase = A + (size_t)m0 * K;
    const __half* Bbase = B + (size_t)n0 * K;

    auto load_stage = [&](int kt, int s) {
        const __half* Ag = Abase + kt * HBK;
        const __half* Bg = Bbase + kt * HBK;
        const uint32_t sa = smem_base + (uint32_t)(s * STAGE_HALVES) * 2u;
        const uint32_t sb = sa + BM * HKP * 2u;
        #pragma unroll
        for (int r = 0; r < 4; r++) {
            const int i   = r * 256 + tid;
            const int row = i >> 3;
            const int kc  = (i & 7) << 3;
            cp16(sa + (uint32_t)(row * HKP + kc) * 2u, Ag + (size_t)row * K + kc);
            cp16(sb + (uint32_t)(row * HKP + kc) * 2u, Bg + (size_t)row * K + kc);
        }
        asm volatile("cp.async.commit_group;");
    };

    load_stage(0, 0);
    load_stage(1, 1);

    float acc[4][4][4];
    #pragma unroll
    for (int a = 0; a < 4; a++)
        #pragma unroll
        for (int b = 0; b < 4; b++)
            #pragma unroll
            for (int c = 0; c < 4; c++) acc[a][b][c] = 0.0f;

    const int nk = K / HBK;
    for (int kt = 0; kt < nk; kt++) {
        asm volatile("cp.async.wait_group 1;");
        __syncthreads();

        if (kt + 2 < nk) load_stage(kt + 2, (kt + 2) % 3);
        else             asm volatile("cp.async.commit_group;");

        const uint32_t st = smem_base + (uint32_t)((kt % 3) * STAGE_HALVES) * 2u;
        const uint32_t aa = st + a_lane;
        const uint32_t bb = st + BM * HKP * 2u + b_lane;

        #pragma unroll
        for (int ks = 0; ks < 4; ks++) {
            const uint32_t k0b = (uint32_t)(ks * 32);
            uint32_t af[4][4], bf[2][4];
            #pragma unroll
            for (int mt = 0; mt < 4; mt++)
                ldsm_x4(af[mt], aa + (uint32_t)(mt * 16 * HKP * 2) + k0b);
            ldsm_x4(bf[0], bb + k0b);
            ldsm_x4(bf[1], bb + (uint32_t)(16 * HKP * 2) + k0b);
            #pragma unroll
            for (int mt = 0; mt < 4; mt++) {
                mma_f16(acc[mt][0], af[mt], &bf[0][0]);
                mma_f16(acc[mt][1], af[mt], &bf[0][2]);
                mma_f16(acc[mt][2], af[mt], &bf[1][0]);
                mma_f16(acc[mt][3], af[mt], &bf[1][2]);
            }
        }
    }
    __syncthreads();

    if (OUT_HALF) {
        __half* C = (__half*)Cv;
        #pragma unroll
        for (int mt = 0; mt < 4; mt++) {
            #pragma unroll
            for (int nt = 0; nt < 4; nt++) {
                const int row = m0 + wm * 64 + mt * 16 + lq;
                const int col = n0 + wn * 32 + nt * 8 + lr * 2;
                float x0 = acc[mt][nt][0], x1 = acc[mt][nt][1];
                float x2 = acc[mt][nt][2], x3 = acc[mt][nt][3];
                if (DO_CLIP) {
                    x0 = fminf(fmaxf(x0, -CLIP_V), CLIP_V);
                    x1 = fminf(fmaxf(x1, -CLIP_V), CLIP_V);
                    x2 = fminf(fmaxf(x2, -CLIP_V), CLIP_V);
                    x3 = fminf(fmaxf(x3, -CLIP_V), CLIP_V);
                }
                *(half2*)(C + (size_t)row * N + col)       = __floats2half2_rn(x0, x1);
                *(half2*)(C + (size_t)(row + 8) * N + col) = __floats2half2_rn(x2, x3);
            }
        }
    } else {
        float* C  = (float*)Cv;
        float* ep = (float*)smc + wid * (64 * EP_PITCH);
        #pragma unroll
        for (int mt = 0; mt < 4; mt++) {
            __syncwarp();
            #pragma unroll
            for (int nt = 0; nt < 4; nt++) {
                float* p0 = ep + (lq)     * EP_PITCH + nt * 8 + lr * 2;
                float* p1 = ep + (lq + 8) * EP_PITCH + nt * 8 + lr * 2;
                p0[0] = acc[mt][nt][0]; p0[1] = acc[mt][nt][1];
                p1[0] = acc[mt][nt][2]; p1[1] = acc[mt][nt][3];
            }
            __syncwarp();
            #pragma unroll
            for (int rr = 0; rr < 4; rr++) {
                const int row = rr * 4 + (ln >> 3);
                const int c4  = (ln & 7) * 4;
                float4 v = *(float4*)&ep[row * EP_PITCH + c4];
                *(float4*)(C + (size_t)(m0 + wm * 64 + mt * 16 + row) * N
                             + n0 + wn * 32 + c4) = v;
            }
        }
    }
}

// ---------------------------------------------------------------------------
// RoPE + layout — sincos hoisted to smem
// ---------------------------------------------------------------------------
__global__ __launch_bounds__(256)
void rope_kernel()
{
    __shared__ float cs[64], sn[64];

    const int token = blockIdx.x;
    const int b    = token / SEQ;
    const int spos = token - b * SEQ;
    const __half* row = g_qkv + (size_t)token * QKV_N;

    if (threadIdx.x < 64) {
        const int j = threadIdx.x;
        const float freq = __powf(500000.0f, -(float)j * (1.0f / 64.0f));
        sincosf((float)spos * freq, &sn[j], &cs[j]);
    }
    __syncthreads();

    for (int idx = threadIdx.x; idx < (NHEADS + KVHEADS) * 64; idx += 256) {
        const int h = idx >> 6;
        const int j = idx & 63;
        const float s = sn[j], c = cs[j];

        const float x1 = __half2float(row[h * HEADDIM + j]);
        const float x2 = __half2float(row[h * HEADDIM + 64 + j]);
        const float y1 = x1 * c - x2 * s;
        const float y2 = x2 * c + x1 * s;

        if (h < NHEADS) {
            __half* q = g_q + ((size_t)(b * NHEADS + h) * SEQ + spos) * HEADDIM;
            q[j]      = __float2half_rn(y1 * INV_SQRT_D);
            q[j + 64] = __float2half_rn(y2 * INV_SQRT_D);
        } else {
            __half* k = g_k + ((size_t)(b * KVHEADS + (h - NHEADS)) * SEQ + spos) * HEADDIM;
            k[j]      = __float2half_rn(y1);
            k[j + 64] = __float2half_rn(y2);
        }
    }

    const __half* vrow = row + DMODEL + KVHEADS * HEADDIM;
    for (int idx = threadIdx.x; idx < KVHEADS * HEADDIM; idx += 256) {
        const int hk = idx >> 7;
        const int d  = idx & 127;
        g_vt[((size_t)(b * KVHEADS + hk) * HEADDIM + d) * SEQ + spos] = vrow[hk * HEADDIM + d];
    }
}

// ---------------------------------------------------------------------------
// FP16 causal flash attention — 2 CTAs/SM, register-resident P.
// The S C-fragment (tiles 2u,2u+1) IS the P A-fragment for k-chunk u:
// no smem round-trip for P. Freed P buffer -> second V buffer (double-
// buffered V, one __syncthreads per iteration).
// smem: Q[128][136] + K0,K1[64][136] + V0,V1[128][72] = 106,496 B.
// ---------------------------------------------------------------------------
#define AK_PITCH 136
#define AV_PITCH 72
#define QB_BYTES (128 * AK_PITCH * 2)   // 34,816
#define AK_BYTES (64 * AK_PITCH * 2)    // 17,408
#define AV_BYTES (128 * AV_PITCH * 2)   // 18,432
#define ATTN_SMEM_BYTES (QB_BYTES + 2 * AK_BYTES + 2 * AV_BYTES) // 106,496
#define NQT (SEQ / 128)                 // 16

__global__ __launch_bounds__(256, 2)
void attn_kernel()
{
    extern __shared__ char smc[];
    const uint32_t smem_base = (uint32_t)__cvta_generic_to_shared(smc);
    const uint32_t qb    = smem_base;
    const uint32_t kb[2] = { smem_base + QB_BYTES,
                             smem_base + QB_BYTES + AK_BYTES };
    const uint32_t vb[2] = { smem_base + QB_BYTES + 2 * AK_BYTES,
                             smem_base + QB_BYTES + 2 * AK_BYTES + AV_BYTES };

    const int qtile = (NQT - 1) - (blockIdx.x / NHEADS);
    const int h     = blockIdx.x % NHEADS;
    const int b     = blockIdx.y;
    const int hk = h >> 2;
    const int q0 = qtile * 128;
    const int nj = 2 * qtile + 2;

    const int tid = threadIdx.x;
    const int ln  = tid & 31;
    const int wid = tid >> 5;
    const int lq  = ln >> 2;
    const int lr  = ln & 3;

    const uint32_t a_lane_q = (uint32_t)(((wid * 16 + (ln & 15)) * AK_PITCH
                                          + (ln >> 4) * 8) * 2);
    const uint32_t b_lane_k = (uint32_t)((((ln >> 4) * 8 + (ln & 7)) * AK_PITCH
                                          + ((ln >> 3) & 1) * 8) * 2);
    const uint32_t b_lane_v = (uint32_t)((((ln >> 4) * 8 + (ln & 7)) * AV_PITCH
                                          + ((ln >> 3) & 1) * 8) * 2);

    const __half* Qg = g_q  + ((size_t)(b * NHEADS  + h)  * SEQ + q0) * HEADDIM;
    const __half* Kg = g_k  + ((size_t)(b * KVHEADS + hk) * SEQ) * HEADDIM;
    const __half* Vg = g_vt + ((size_t)(b * KVHEADS + hk) * HEADDIM) * SEQ;

    auto load_k = [&](int jt) {
        const int j0 = jt * 64;
        const uint32_t base = kb[jt & 1];
        for (int i = tid; i < 1024; i += 256) {
            const int r  = i >> 4;
            const int c8 = (i & 15) << 3;
            cp16(base + (uint32_t)(r * AK_PITCH + c8) * 2u,
                 Kg + (size_t)(j0 + r) * HEADDIM + c8);
        }
        asm volatile("cp.async.commit_group;");
    };
    auto load_v = [&](int jt) {
        const int j0 = jt * 64;
        const uint32_t base = vb[jt & 1];
        for (int i = tid; i < 1024; i += 256) {
            const int r  = i >> 3;
            const int c8 = (i & 7) << 3;
            cp16(base + (uint32_t)(r * AV_PITCH + c8) * 2u,
                 Vg + (size_t)r * SEQ + j0 + c8);
        }
        asm volatile("cp.async.commit_group;");
    };

    // ---- prologue: Q into its persistent buffer ----
    for (int i = tid; i < 2048; i += 256) {
        const int r  = i >> 4;
        const int c8 = (i & 15) << 3;
        cp16(qb + (uint32_t)(r * AK_PITCH + c8) * 2u, Qg + (size_t)r * HEADDIM + c8);
    }
    asm volatile("cp.async.commit_group;");
    asm volatile("cp.async.wait_group 0;");
    __syncthreads();

    load_k(0);
    load_v(0);

    float m0 = -3.0e38f, m1 = -3.0e38f, l0 = 0.0f, l1 = 0.0f;
    float o[16][4];
    #pragma unroll
    for (int nt = 0; nt < 16; nt++)
        #pragma unroll
        for (int c = 0; c < 4; c++) o[nt][c] = 0.0f;

    for (int jt = 0; jt < nj; jt++) {
        asm volatile("cp.async.wait_group 1;");   // K(jt) done (V(jt) may pend)
        __syncthreads();                          // old buffers fully consumed

        // ---- S = Q K^T (Q fragments ldsm'd from persistent buffer) ----
        float s_[8][4];
        #pragma unroll
        for (int t = 0; t < 8; t++)
            #pragma unroll
            for (int c = 0; c < 4; c++) s_[t][c] = 0.0f;

        const uint32_t kbase = kb[jt & 1] + b_lane_k;
        #pragma unroll
        for (int ks = 0; ks < 8; ks++) {
            const uint32_t k0b = (uint32_t)(ks * 32);
            uint32_t qf[4];
            ldsm_x4(qf, qb + a_lane_q + k0b);
            #pragma unroll
            for (int p = 0; p < 4; p++) {
                uint32_t bt[4];
                ldsm_x4(bt, kbase + (uint32_t)(p * 16 * AK_PITCH * 2) + k0b);
                mma_f16(s_[2 * p],     qf, &bt[0]);
                mma_f16(s_[2 * p + 1], qf, &bt[2]);
            }
        }

        if (jt + 1 < nj) load_k(jt + 1);
        else             asm volatile("cp.async.commit_group;");

        if (jt >= nj - 2) {                       // causal mask (last two tiles)
            const int rrel  = wid * 16 + lq;
            const int crel0 = (jt - (nj - 2)) * 64;
            #pragma unroll
            for (int t = 0; t < 8; t++) {
                const int c0 = crel0 + t * 8 + 2 * lr;
                if (c0     > rrel)     s_[t][0] = -3.0e38f;
                if (c0 + 1 > rrel)     s_[t][1] = -3.0e38f;
                if (c0     > rrel + 8) s_[t][2] = -3.0e38f;
                if (c0 + 1 > rrel + 8) s_[t][3] = -3.0e38f;
            }
        }

        // ---- online softmax ----
        float mx0 = -3.0e38f, mx1 = -3.0e38f;
        #pragma unroll
        for (int t = 0; t < 8; t++) {
            mx0 = fmaxf(mx0, fmaxf(s_[t][0], s_[t][1]));
            mx1 = fmaxf(mx1, fmaxf(s_[t][2], s_[t][3]));
        }
        mx0 = fmaxf(mx0, __shfl_xor_sync(0xffffffffu, mx0, 1));
        mx0 = fmaxf(mx0, __shfl_xor_sync(0xffffffffu, mx0, 2));
        mx1 = fmaxf(mx1, __shfl_xor_sync(0xffffffffu, mx1, 1));
        mx1 = fmaxf(mx1, __shfl_xor_sync(0xffffffffu, mx1, 2));

        const float mn0 = fmaxf(m0, mx0);
        const float mn1 = fmaxf(m1, mx1);
        const float al0 = __expf(m0 - mn0);
        const float al1 = __expf(m1 - mn1);
        float rs0 = 0.0f, rs1 = 0.0f;
        #pragma unroll
        for (int t = 0; t < 8; t++) {
            s_[t][0] = __expf(s_[t][0] - mn0); rs0 += s_[t][0];
            s_[t][1] = __expf(s_[t][1] - mn0); rs0 += s_[t][1];
            s_[t][2] = __expf(s_[t][2] - mn1); rs1 += s_[t][2];
            s_[t][3] = __expf(s_[t][3] - mn1); rs1 += s_[t][3];
        }
        rs0 += __shfl_xor_sync(0xffffffffu, rs0, 1);
        rs0 += __shfl_xor_sync(0xffffffffu, rs0, 2);
        rs1 += __shfl_xor_sync(0xffffffffu, rs1, 1);
        rs1 += __shfl_xor_sync(0xffffffffu, rs1, 2);
        l0 = l0 * al0 + rs0;  m0 = mn0;
        l1 = l1 * al1 + rs1;  m1 = mn1;
        #pragma unroll
        for (int nt = 0; nt < 16; nt++) {
            o[nt][0] *= al0; o[nt][1] *= al0;
            o[nt][2] *= al1; o[nt][3] *= al1;
        }

        // ---- P -> register A-fragments (C-frag of tiles 2u,2u+1 == A-frag) ----
        uint32_t pa[4][4];
        #pragma unroll
        for (int u = 0; u < 4; u++) {
            pa[u][0] = pkh2(s_[2 * u][0],     s_[2 * u][1]);
            pa[u][1] = pkh2(s_[2 * u][2],     s_[2 * u][3]);
            pa[u][2] = pkh2(s_[2 * u + 1][0], s_[2 * u + 1][1]);
            pa[u][3] = pkh2(s_[2 * u + 1][2], s_[2 * u + 1][3]);
        }

        asm volatile("cp.async.wait_group 1;");   // V(jt) done (K(jt+1) may pend)

        // ---- O += P Vt ----
        const uint32_t vbase = vb[jt & 1] + b_lane_v;
        #pragma unroll
        for (int u = 0; u < 4; u++) {
            const uint32_t k0b = (uint32_t)(u * 32);
            #pragma unroll
            for (int p = 0; p < 8; p++) {
                uint32_t bt[4];
                ldsm_x4(bt, vbase + (uint32_t)(p * 16 * AV_PITCH * 2) + k0b);
                mma_f16(o[2 * p],     pa[u], &bt[0]);
                mma_f16(o[2 * p + 1], pa[u], &bt[2]);
            }
        }

        if (jt + 1 < nj) load_v(jt + 1);
        else             asm volatile("cp.async.commit_group;");
    }

    // ---- epilogue ----
    const float inv0 = 1.0f / l0;
    const float inv1 = 1.0f / l1;
    const int s0 = q0 + wid * 16 + lq;
    __half* O0 = g_attn + (size_t)(b * SEQ + s0) * DMODEL + h * HEADDIM + 2 * lr;
    __half* O1 = O0 + (size_t)8 * DMODEL;
    #pragma unroll
    for (int nt = 0; nt < 16; nt++) {
        *(half2*)(O0 + nt * 8) = __floats2half2_rn(o[nt][0] * inv0, o[nt][1] * inv0);
        *(half2*)(O1 + nt * 8) = __floats2half2_rn(o[nt][2] * inv1, o[nt][3] * inv1);
    }
}

// ---------------------------------------------------------------------------
// Launch sequence
// ---------------------------------------------------------------------------
extern "C" void kernel_launch(void* const* d_in, const int* in_sizes, int n_in,
                              void* d_out, int out_size)
{
    const float* hidden = (const float*)d_in[0];
    const float* Wqkv   = (const float*)d_in[3];
    const float* out_w  = (const float*)d_in[4];
    float*       out    = (float*)d_out;

    __half *qkv_p, *attn_p, *hid_p, *wq_p, *wo_p;
    cudaGetSymbolAddress((void**)&qkv_p,  g_qkv);
    cudaGetSymbolAddress((void**)&attn_p, g_attn);
    cudaGetSymbolAddress((void**)&hid_p,  g_hid);
    cudaGetSymbolAddress((void**)&wq_p,   g_wq);
    cudaGetSymbolAddress((void**)&wo_p,   g_wo);

    cudaFuncSetAttribute((const void*)gemm_f16<true, true>,
                         cudaFuncAttributeMaxDynamicSharedMemorySize, GEMM_SMEM_BYTES);
    cudaFuncSetAttribute((const void*)gemm_f16<false, false>,
                         cudaFuncAttributeMaxDynamicSharedMemorySize, GEMM_SMEM_BYTES);
    cudaFuncSetAttribute((const void*)attn_kernel,
                         cudaFuncAttributeMaxDynamicSharedMemorySize, ATTN_SMEM_BYTES);

    // 0) fused fp16 pre-round (one launch)
    round_all_kernel<<<1184, 256>>>((const float4*)hidden, (const float4*)Wqkv,
                                    (const float4*)out_w,
                                    (half2*)hid_p, (half2*)wq_p, (half2*)wo_p);

    // 1) QKV projection with clip (half output)
    gemm_f16<true, true><<<dim3(QKV_N / BN, TOKENS / BM), 256, GEMM_SMEM_BYTES>>>(
        hid_p, wq_p, qkv_p, TOKENS, QKV_N, DMODEL);

    // 2) RoPE + layouts
    rope_kernel<<<TOKENS, 256>>>();

    // 3) fp16 causal flash attention (2 CTAs/SM, register-resident P)
    attn_kernel<<<dim3(NQT * NHEADS, BATCH), 256, ATTN_SMEM_BYTES>>>();

    // 4) output projection (f32 output)
    gemm_f16<false, false><<<dim3(DMODEL / BN, TOKENS / BM), 256, GEMM_SMEM_BYTES>>>(
        attn_p, wo_p, out, TOKENS, DMODEL, DMODEL);
}